// round 9
// baseline (speedup 1.0000x reference)
#include <cuda_runtime.h>
#include <cuda_fp16.h>
#include <math.h>

// ---------------- dims ----------------
#define BB    8
#define NNODE 1024
#define DD    256
#define HH    8
#define DHH   32
#define DFFX  1024
#define LGN   2
#define LTN   2
#define NBCAP 256
#define MTOT  (BB*NNODE)

// ---------------- scratch (device globals; no runtime allocation) ----------------
__device__ float                 g_XC[MTOT*DD];
__device__ __align__(16) __half  g_XCH[MTOT*DD];
__device__ __align__(16) __half  g_EMBH[MTOT*DD];
__device__ __align__(16) __half  g_HBH[MTOT*HH*DD];
__device__ __align__(16) signed char g_HQ[MTOT*HH*DD];
__device__ float                 g_HS[MTOT*HH];
__device__ float                 g_AS[MTOT*HH];
__device__ float                 g_AD[MTOT*HH];
__device__ float                 g_ASP[32*MTOT];
__device__ float                 g_ADP[32*MTOT];
__device__ __align__(16) __half  g_QKVH[MTOT*3*DD];
__device__ __align__(16) __half  g_WQKVH[LTN*DD*3*DD];
__device__ float                 g_BQKV[LTN*3*DD];
__device__ __align__(16) __half  g_GATWH[LGN*HH*DD*DD];
__device__ __align__(16) __half  g_WOH[LTN*DD*DD];
__device__ __align__(16) __half  g_W1H[LTN*DD*DFFX];
__device__ __align__(16) __half  g_W2H[LTN*DFFX*DD];
__device__ __align__(16) __half  g_AOH[MTOT*DD];
__device__ float                 g_Y [MTOT*DD];
__device__ __align__(16) __half  g_YH[MTOT*DD];
__device__ __align__(16) __half  g_FFH[MTOT*DFFX];
__device__ unsigned              g_BITS[MTOT*(NNODE/32)];
__device__ int                   g_NBR[MTOT*NBCAP];
__device__ int                   g_CNT[MTOT];

// ---------------- helpers ----------------
__device__ __forceinline__ void mma_f16(float* c, const unsigned* a, const unsigned* b) {
    asm volatile(
        "mma.sync.aligned.m16n8k16.row.col.f32.f16.f16.f32 "
        "{%0,%1,%2,%3}, {%4,%5,%6,%7}, {%8,%9}, {%0,%1,%2,%3};\n"
        : "+f"(c[0]), "+f"(c[1]), "+f"(c[2]), "+f"(c[3])
        : "r"(a[0]), "r"(a[1]), "r"(a[2]), "r"(a[3]), "r"(b[0]), "r"(b[1]));
}

__device__ __forceinline__ unsigned saddr(const void* p) {
    return (unsigned)__cvta_generic_to_shared(p);
}
__device__ __forceinline__ void cp16(unsigned dst, const void* src) {
    asm volatile("cp.async.cg.shared.global [%0], [%1], 16;\n" :: "r"(dst), "l"(src));
}
__device__ __forceinline__ void cp_commit() {
    asm volatile("cp.async.commit_group;\n" ::: "memory");
}
template<int N>
__device__ __forceinline__ void cp_wait() {
    asm volatile("cp.async.wait_group %0;\n" :: "n"(N) : "memory");
}
__device__ __forceinline__ void ldsm4(unsigned& r0, unsigned& r1, unsigned& r2, unsigned& r3,
                                      unsigned addr) {
    asm volatile("ldmatrix.sync.aligned.m8n8.x4.shared.b16 {%0,%1,%2,%3}, [%4];"
                 : "=r"(r0), "=r"(r1), "=r"(r2), "=r"(r3) : "r"(addr));
}
__device__ __forceinline__ void ldsm4t(unsigned& r0, unsigned& r1, unsigned& r2, unsigned& r3,
                                       unsigned addr) {
    asm volatile("ldmatrix.sync.aligned.m8n8.x4.trans.shared.b16 {%0,%1,%2,%3}, [%4];"
                 : "=r"(r0), "=r"(r1), "=r"(r2), "=r"(r3) : "r"(addr));
}

// ---------------- adjacency pack ----------------
__global__ void pack_adj_k(const int* __restrict__ mask, unsigned* __restrict__ bits) {
    int idx = blockIdx.x * blockDim.x + threadIdx.x;
    int t  = idx & (NNODE - 1);
    int sw = (idx >> 10) & 31;
    int b  = idx >> 15;
    const int* mp = mask + ((size_t)b * NNODE + (size_t)sw * 32) * NNODE + t;
    unsigned w = 0;
    #pragma unroll
    for (int i = 0; i < 32; i++)
        if (mp[(size_t)i * NNODE] > 0) w |= (1u << i);
    int s0 = sw * 32;
    if (t >= s0 && t < s0 + 32) w |= (1u << (t - s0));
    bits[(b * NNODE + t) * 32 + sw] = w;
}

// ---------------- neighbor list build ----------------
__global__ void build_nbr_k(const unsigned* __restrict__ bits,
                            int* __restrict__ nbr, int* __restrict__ cnt) {
    int bt = blockIdx.x * blockDim.x + threadIdx.x;
    if (bt >= MTOT) return;
    const unsigned* bw = bits + (size_t)bt * 32;
    int* np = nbr + (size_t)bt * NBCAP;
    int c = 0;
    #pragma unroll 4
    for (int w = 0; w < 32; w++) {
        unsigned m = bw[w];
        while (m) {
            int bit = __ffs(m) - 1;
            m &= m - 1;
            if (c < NBCAP) np[c] = w * 32 + bit;
            c++;
        }
    }
    cnt[bt] = c < NBCAP ? c : NBCAP;
}

// ---------------- generic fp32 -> fp16 convert ----------------
__global__ void cvt_half_k(const float* __restrict__ src, __half* __restrict__ dst, int n) {
    int i = blockIdx.x * 256 + threadIdx.x;
    if (i * 4 >= n) return;
    float4 v = *(const float4*)(src + i * 4);
    *(__half2*)(dst + i * 4)     = __floats2half2_rn(v.x, v.y);
    *(__half2*)(dst + i * 4 + 2) = __floats2half2_rn(v.z, v.w);
}

// ---------------- QKV pack ----------------
__global__ void pack_qkv_k(const float* __restrict__ Wq, const float* __restrict__ Wk,
                           const float* __restrict__ Wv, const float* __restrict__ bq,
                           const float* __restrict__ bk, const float* __restrict__ bv,
                           __half* __restrict__ W, float* __restrict__ Bb)
{
    int idx = blockIdx.x * 256 + threadIdx.x;
    if (idx >= LTN * DD * 3 * DD) return;
    int n = idx % (3 * DD);
    int k = (idx / (3 * DD)) % DD;
    int l = idx / (3 * DD * DD);
    float v;
    if (n < DD)            v = Wq[((size_t)l * DD + k) * DD + n];
    else if (n < 2 * DD)   v = Wk[((size_t)l * DD + k) * DD + n - DD];
    else                   v = Wv[((size_t)l * DD + k) * DD + n - 2 * DD];
    W[idx] = __float2half_rn(v);
    if (k == 0) {
        float bvv;
        if (n < DD)          bvv = bq[l * DD + n];
        else if (n < 2 * DD) bvv = bk[l * DD + n - DD];
        else                 bvv = bv[l * DD + n - 2 * DD];
        Bb[l * 3 * DD + n] = bvv;
    }
}

// ---------------- fp16 tensor-core GEMM: cp.async + ldmatrix ----------------
template<bool BT, int ACT, int HALF_OUT, int ASAD>
__global__ void __launch_bounds__(256) hgemm_k(
    int M, int Ncol, int K,
    const __half* __restrict__ A, int lda,
    const __half* __restrict__ B, int ldb,
    void* __restrict__ Cv, int ldc,
    const float* __restrict__ bias,
    const float* __restrict__ attS, const float* __restrict__ attD,
    float* __restrict__ ASP, float* __restrict__ ADP)
{
    __shared__ __align__(16) __half sA[2][128 * 24];
    __shared__ __align__(16) __half sB[2][3072];
    const int tid  = threadIdx.x;
    const int lane = tid & 31, wid = tid >> 5;
    const int wm = wid & 3, wn = wid >> 2;
    const int m0 = blockIdx.y * 128, n0 = blockIdx.x * 128;
    const int r = lane >> 2, cq = lane & 3;

    float acc[2][8][4];
    #pragma unroll
    for (int mt = 0; mt < 2; mt++)
        #pragma unroll
        for (int nt = 0; nt < 8; nt++)
            #pragma unroll
            for (int u = 0; u < 4; u++) acc[mt][nt][u] = 0.f;

    const int T = K / 16;

    auto loadT = [&](int st, int k0) {
        {
            int m = tid >> 1, c = tid & 1;
            cp16(saddr(&sA[st][m * 24 + c * 8]), A + (size_t)(m0 + m) * lda + k0 + c * 8);
        }
        if (BT) {
            int n = tid >> 1, c = tid & 1;
            cp16(saddr(&sB[st][n * 24 + c * 8]), B + (size_t)(n0 + n) * ldb + k0 + c * 8);
        } else {
            int kk = tid >> 4, c = tid & 15;
            cp16(saddr(&sB[st][kk * 136 + c * 8]), B + (size_t)(k0 + kk) * ldb + n0 + c * 8);
        }
        cp_commit();
    };

    loadT(0, 0);
    for (int t = 0; t < T; t++) {
        if (t + 1 < T) { loadT((t + 1) & 1, (t + 1) * 16); cp_wait<1>(); }
        else           { cp_wait<0>(); }
        __syncthreads();
        const int st = t & 1;

        unsigned af[2][4], bf[8][2];
        #pragma unroll
        for (int mt = 0; mt < 2; mt++) {
            int mrow = wm * 32 + mt * 16;
            unsigned addr = saddr(&sA[st][(mrow + (lane & 15)) * 24 + (lane >> 4) * 8]);
            ldsm4(af[mt][0], af[mt][1], af[mt][2], af[mt][3], addr);
        }
        #pragma unroll
        for (int p = 0; p < 4; p++) {
            int nb = wn * 64 + p * 16;
            if (BT) {
                int row = nb + (lane & 7) + ((lane >> 4) << 3);
                int col = ((lane >> 3) & 1) * 8;
                unsigned addr = saddr(&sB[st][row * 24 + col]);
                ldsm4(bf[2 * p][0], bf[2 * p][1], bf[2 * p + 1][0], bf[2 * p + 1][1], addr);
            } else {
                int krow = (lane & 7) + (((lane >> 3) & 1) << 3);
                int coln = nb + (lane >> 4) * 8;
                unsigned addr = saddr(&sB[st][krow * 136 + coln]);
                ldsm4t(bf[2 * p][0], bf[2 * p][1], bf[2 * p + 1][0], bf[2 * p + 1][1], addr);
            }
        }
        #pragma unroll
        for (int mt = 0; mt < 2; mt++)
            #pragma unroll
            for (int nt = 0; nt < 8; nt++)
                mma_f16(acc[mt][nt], af[mt], bf[nt]);
        __syncthreads();
    }

    if (ASAD) {
        float sS[2][2] = {{0,0},{0,0}}, sD[2][2] = {{0,0},{0,0}};
        #pragma unroll
        for (int mt = 0; mt < 2; mt++)
            #pragma unroll
            for (int nt = 0; nt < 8; nt++)
                #pragma unroll
                for (int u = 0; u < 4; u++) {
                    int g = n0 + wn * 64 + nt * 8 + cq * 2 + (u & 1);
                    float v = acc[mt][nt][u];
                    sS[mt][u >> 1] += v * attS[g];
                    sD[mt][u >> 1] += v * attD[g];
                }
        #pragma unroll
        for (int o = 1; o <= 2; o <<= 1)
            #pragma unroll
            for (int mt = 0; mt < 2; mt++)
                #pragma unroll
                for (int q = 0; q < 2; q++) {
                    sS[mt][q] += __shfl_xor_sync(0xffffffffu, sS[mt][q], o);
                    sD[mt][q] += __shfl_xor_sync(0xffffffffu, sD[mt][q], o);
                }
        if (cq == 0) {
            int j = (n0 >> 6) + wn;
            #pragma unroll
            for (int mt = 0; mt < 2; mt++)
                #pragma unroll
                for (int q = 0; q < 2; q++) {
                    int row = m0 + wm * 32 + mt * 16 + r + q * 8;
                    ASP[(size_t)j * M + row] = sS[mt][q];
                    ADP[(size_t)j * M + row] = sD[mt][q];
                }
        }
    }

    #pragma unroll
    for (int mt = 0; mt < 2; mt++) {
        int mrow = m0 + wm * 32 + mt * 16 + r;
        #pragma unroll
        for (int nt = 0; nt < 8; nt++) {
            int ncol = n0 + wn * 64 + nt * 8 + cq * 2;
            float* ac = acc[mt][nt];
            float2 v0 = make_float2(ac[0], ac[1]);
            float2 v1 = make_float2(ac[2], ac[3]);
            if (bias) {
                float b0 = bias[ncol], b1 = bias[ncol + 1];
                v0.x += b0; v0.y += b1; v1.x += b0; v1.y += b1;
            }
            if (ACT == 1) {
                v0.x = fmaxf(v0.x, 0.f); v0.y = fmaxf(v0.y, 0.f);
                v1.x = fmaxf(v1.x, 0.f); v1.y = fmaxf(v1.y, 0.f);
            }
            if (HALF_OUT) {
                __half* Ch = (__half*)Cv;
                *(__half2*)(Ch + (size_t)mrow * ldc + ncol) = __floats2half2_rn(v0.x, v0.y);
                *(__half2*)(Ch + (size_t)(mrow + 8) * ldc + ncol) = __floats2half2_rn(v1.x, v1.y);
            } else {
                float* Cf = (float*)Cv;
                *(float2*)(Cf + (size_t)mrow * ldc + ncol) = v0;
                *(float2*)(Cf + (size_t)(mrow + 8) * ldc + ncol) = v1;
            }
        }
    }
}

// ---------------- asad reduce ----------------
__global__ void asad_reduce_k(const float* __restrict__ ASP, const float* __restrict__ ADP,
                              float* __restrict__ as_, float* __restrict__ ad_)
{
    int idx = blockIdx.x * 256 + threadIdx.x;
    int row = idx >> 3, h = idx & 7;
    float s = 0.f, d = 0.f;
    #pragma unroll
    for (int j = 4 * h; j < 4 * h + 4; j++) {
        s += ASP[(size_t)j * MTOT + row];
        d += ADP[(size_t)j * MTOT + row];
    }
    as_[row * 8 + h] = s;
    ad_[row * 8 + h] = d;
}

// ---------------- int8 quantization of GAT features: warp per (node,head) ----------------
__global__ void __launch_bounds__(256) quant_h_k(
    const __half* __restrict__ hb, signed char* __restrict__ hq,
    float* __restrict__ hs)
{
    int nh   = blockIdx.x * 8 + (threadIdx.x >> 5);
    int lane = threadIdx.x & 31;
    const float4* src = (const float4*)(hb + (size_t)nh * 256);
    float4 raw = src[lane];
    const __half2* h2 = (const __half2*)&raw;
    float f[8];
    #pragma unroll
    for (int i = 0; i < 4; i++) {
        float2 p = __half22float2(h2[i]);
        f[2 * i] = p.x; f[2 * i + 1] = p.y;
    }
    float m = 0.f;
    #pragma unroll
    for (int i = 0; i < 8; i++) m = fmaxf(m, fabsf(f[i]));
    #pragma unroll
    for (int o = 16; o; o >>= 1) m = fmaxf(m, __shfl_xor_sync(0xffffffffu, m, o));
    float inv = m > 0.f ? 127.f / m : 0.f;
    if (lane == 0) hs[nh] = m * (1.f / 127.f);
    int q[8];
    #pragma unroll
    for (int i = 0; i < 8; i++) {
        int v = __float2int_rn(f[i] * inv);
        q[i] = v > 127 ? 127 : (v < -127 ? -127 : v);
    }
    unsigned lo = (q[0] & 255) | ((q[1] & 255) << 8) | ((q[2] & 255) << 16) | ((unsigned)(q[3] & 255) << 24);
    unsigned hi = (q[4] & 255) | ((q[5] & 255) << 8) | ((q[6] & 255) << 16) | ((unsigned)(q[7] & 255) << 24);
    *(uint2*)(hq + (size_t)nh * 256 + lane * 8) = make_uint2(lo, hi);
}

// ---------------- sparse GAT aggregation (int8; warp = head, lane = 8 cols) ----------------
__global__ void __launch_bounds__(256) gat_agg_k(
    const signed char* __restrict__ hq, const float* __restrict__ hs,
    const float* __restrict__ as_, const float* __restrict__ ad_,
    const int* __restrict__ nbr, const int* __restrict__ cnt,
    const float* __restrict__ bias,
    float* __restrict__ y, __half* __restrict__ yh)
{
    __shared__ int   s_nbr[NBCAP];
    __shared__ float s_alpha[HH][NBCAP];
    __shared__ float s_inv[HH];
    __shared__ float s_red[HH][DD];
    int bt  = blockIdx.x;
    int b   = bt >> 10;
    int tid = threadIdx.x;
    int nc  = cnt[bt];
    for (int j = tid; j < nc; j += 256) s_nbr[j] = nbr[(size_t)bt * NBCAP + j];
    __syncthreads();

    // unnormalized weights
    for (int j = tid; j < nc; j += 256) {
        int s = s_nbr[j];
        const float* ap = as_ + (size_t)(b * NNODE + s) * HH;
        #pragma unroll
        for (int h = 0; h < HH; h++) {
            float e = ad_[bt * HH + h] + ap[h];
            e = e >= 0.f ? e : 0.2f * e;
            s_alpha[h][j] = __expf(e);
        }
    }
    __syncthreads();

    int h    = tid >> 5;       // warp = head
    int lane = tid & 31;
    {
        float sum = 0.f;
        for (int j = lane; j < nc; j += 32) sum += s_alpha[h][j];
        #pragma unroll
        for (int o = 16; o; o >>= 1) sum += __shfl_xor_sync(0xffffffffu, sum, o);
        if (lane == 0) s_inv[h] = 1.f / (8.f * sum);
    }
    __syncthreads();
    // normalize and fold per-(source,head) dequant scale into alpha
    for (int j = tid; j < nc; j += 256) {
        size_t nb = (size_t)(b * NNODE + s_nbr[j]);
        const float4* hp = (const float4*)(hs + nb * HH);
        float4 s0 = hp[0], s1 = hp[1];
        s_alpha[0][j] *= s_inv[0] * s0.x;
        s_alpha[1][j] *= s_inv[1] * s0.y;
        s_alpha[2][j] *= s_inv[2] * s0.z;
        s_alpha[3][j] *= s_inv[3] * s0.w;
        s_alpha[4][j] *= s_inv[4] * s1.x;
        s_alpha[5][j] *= s_inv[5] * s1.y;
        s_alpha[6][j] *= s_inv[6] * s1.z;
        s_alpha[7][j] *= s_inv[7] * s1.w;
    }
    __syncthreads();

    // gather: lane owns cols [lane*8, lane*8+8) of head h — 1 LDG.64 per edge
    const signed char* hbase = hq + (size_t)b * NNODE * (HH * DD) + h * DD + lane * 8;
    float a[8];
    #pragma unroll
    for (int i = 0; i < 8; i++) a[i] = 0.f;
    #pragma unroll 2
    for (int j = 0; j < nc; j++) {
        float w = s_alpha[h][j];
        uint2 u = *(const uint2*)(hbase + (size_t)s_nbr[j] * (HH * DD));
        char4 c0 = *(char4*)&u.x;
        char4 c1 = *(char4*)&u.y;
        a[0] = fmaf(w, (float)c0.x, a[0]);
        a[1] = fmaf(w, (float)c0.y, a[1]);
        a[2] = fmaf(w, (float)c0.z, a[2]);
        a[3] = fmaf(w, (float)c0.w, a[3]);
        a[4] = fmaf(w, (float)c1.x, a[4]);
        a[5] = fmaf(w, (float)c1.y, a[5]);
        a[6] = fmaf(w, (float)c1.z, a[6]);
        a[7] = fmaf(w, (float)c1.w, a[7]);
    }
    #pragma unroll
    for (int i = 0; i < 8; i += 4)
        *(float4*)&s_red[h][lane * 8 + i] = make_float4(a[i], a[i+1], a[i+2], a[i+3]);
    __syncthreads();

    // sum over heads
    {
        int c = tid;
        float v = bias[c];
        #pragma unroll
        for (int hh = 0; hh < HH; hh++) v += s_red[hh][c];
        y[(size_t)bt * DD + c] = v;
        yh[(size_t)bt * DD + c] = __float2half_rn(v);
    }
}

// ---------------- sparse masked attention (fp16 QKV) ----------------
__global__ void __launch_bounds__(256) attn_sparse_k(
    const __half* __restrict__ QKV, const int* __restrict__ nbr,
    const int* __restrict__ cnt, __half* __restrict__ Om)
{
    __shared__ int s_nbr[NBCAP];
    int bt  = blockIdx.x;
    int b   = bt >> 10;
    int tid = threadIdx.x;
    int nc  = cnt[bt];
    for (int j = tid; j < nc; j += 256) s_nbr[j] = nbr[(size_t)bt * NBCAP + j];
    __syncthreads();
    int h = tid >> 5, lane = tid & 31;
    const int LD3 = 3 * DD;
    float q = __half2float(QKV[(size_t)bt * LD3 + h * DHH + lane]) * 0.17677669529663687f;
    float accv = 0.f, accw = 0.f;
    int j = 0;
    for (; j + 4 <= nc; j += 4) {
        float d[4], vv[4];
        #pragma unroll
        for (int u = 0; u < 4; u++) {
            int s = s_nbr[j + u];
            size_t base = (size_t)(b * NNODE + s) * LD3 + h * DHH + lane;
            d[u]  = q * __half2float(QKV[base + DD]);
            vv[u] = __half2float(QKV[base + 2 * DD]);
        }
        #pragma unroll
        for (int o = 16; o; o >>= 1) {
            #pragma unroll
            for (int u = 0; u < 4; u++) d[u] += __shfl_xor_sync(0xffffffffu, d[u], o);
        }
        #pragma unroll
        for (int u = 0; u < 4; u++) {
            float w = __expf(d[u]);
            accv = fmaf(w, vv[u], accv);
            accw += w;
        }
    }
    for (; j < nc; j++) {
        int s = s_nbr[j];
        size_t base = (size_t)(b * NNODE + s) * LD3 + h * DHH + lane;
        float d = q * __half2float(QKV[base + DD]);
        float vvv = __half2float(QKV[base + 2 * DD]);
        #pragma unroll
        for (int o = 16; o; o >>= 1) d += __shfl_xor_sync(0xffffffffu, d, o);
        float w = __expf(d);
        accv = fmaf(w, vvv, accv);
        accw += w;
    }
    Om[(size_t)bt * DD + h * DHH + lane] = __float2half_rn(accv / accw);
}

// ---------------- layernorm: warp per row ----------------
template<int MODE, int WRITEH>
__global__ void __launch_bounds__(256) ln_warp_k(
    const float* __restrict__ a, const float* __restrict__ bsrc,
    const float* __restrict__ gam, const float* __restrict__ bet,
    float* __restrict__ out, __half* __restrict__ outh)
{
    int row  = blockIdx.x * 8 + (threadIdx.x >> 5);
    int lane = threadIdx.x & 31;
    size_t base = (size_t)row * DD;
    float v[8];
    float sum = 0.f;
    #pragma unroll
    for (int p = 0; p < 2; p++) {
        int c = lane * 4 + p * 128;
        float4 av = *(const float4*)(a + base + c);
        float4 bv = *(const float4*)(bsrc + base + c);
        if (MODE == 1) {
            bv.x = fmaxf(bv.x, 0.f); bv.y = fmaxf(bv.y, 0.f);
            bv.z = fmaxf(bv.z, 0.f); bv.w = fmaxf(bv.w, 0.f);
        }
        v[p*4+0] = av.x + bv.x; v[p*4+1] = av.y + bv.y;
        v[p*4+2] = av.z + bv.z; v[p*4+3] = av.w + bv.w;
        sum += v[p*4+0] + v[p*4+1] + v[p*4+2] + v[p*4+3];
    }
    #pragma unroll
    for (int o = 16; o; o >>= 1) sum += __shfl_xor_sync(0xffffffffu, sum, o);
    float mean = sum * (1.f / DD);
    float var = 0.f;
    #pragma unroll
    for (int i = 0; i < 8; i++) { float d = v[i] - mean; var += d * d; }
    #pragma unroll
    for (int o = 16; o; o >>= 1) var += __shfl_xor_sync(0xffffffffu, var, o);
    float rstd = rsqrtf(var * (1.f / DD) + 1e-5f);
    #pragma unroll
    for (int p = 0; p < 2; p++) {
        int c = lane * 4 + p * 128;
        float4 g = *(const float4*)(gam + c);
        float4 bb = *(const float4*)(bet + c);
        float4 o4;
        o4.x = (v[p*4+0] - mean) * rstd * g.x + bb.x;
        o4.y = (v[p*4+1] - mean) * rstd * g.y + bb.y;
        o4.z = (v[p*4+2] - mean) * rstd * g.z + bb.z;
        o4.w = (v[p*4+3] - mean) * rstd * g.w + bb.w;
        *(float4*)(out + base + c) = o4;
        if (WRITEH) {
            __half2 h0 = __floats2half2_rn(o4.x, o4.y);
            __half2 h1 = __floats2half2_rn(o4.z, o4.w);
            *(uint2*)(outh + base + c) = make_uint2(*(unsigned*)&h0, *(unsigned*)&h1);
        }
    }
}

extern "C" void kernel_launch(void* const* d_in, const int* in_sizes, int n_in,
                              void* d_out, int out_size)
{
    const float* emb  = (const float*)d_in[0];
    const int*   mask = (const int*)  d_in[2];
    const float* gatW = (const float*)d_in[4];
    const float* attS = (const float*)d_in[5];
    const float* attD = (const float*)d_in[6];
    const float* gatB = (const float*)d_in[7];
    const float* glnS = (const float*)d_in[8];
    const float* glnB = (const float*)d_in[9];
    const float* Wq = (const float*)d_in[10], *bq = (const float*)d_in[11];
    const float* Wk = (const float*)d_in[12], *bk = (const float*)d_in[13];
    const float* Wv = (const float*)d_in[14], *bv = (const float*)d_in[15];
    const float* Wo = (const float*)d_in[16], *bo = (const float*)d_in[17];
    const float* W1 = (const float*)d_in[18], *b1 = (const float*)d_in[19];
    const float* W2 = (const float*)d_in[20], *b2 = (const float*)d_in[21];
    const float* l1s = (const float*)d_in[22], *l1b = (const float*)d_in[23];
    const float* l2s = (const float*)d_in[24], *l2b = (const float*)d_in[25];
    float* out = (float*)d_out;

    float *XC,*AS,*AD,*ASP,*ADP,*BQKV,*Y,*HS;
    __half *XCH,*EMBH,*HBH,*QKVH,*WQKVH,*GATWH,*WOH,*W1H,*W2H,*AOH,*YH,*FFH;
    signed char* HQ;
    unsigned* BITS; int *NBR,*CNT;
    cudaGetSymbolAddress((void**)&XC, g_XC);
    cudaGetSymbolAddress((void**)&XCH, g_XCH);
    cudaGetSymbolAddress((void**)&EMBH, g_EMBH);
    cudaGetSymbolAddress((void**)&HBH, g_HBH);
    cudaGetSymbolAddress((void**)&HQ, g_HQ);
    cudaGetSymbolAddress((void**)&HS, g_HS);
    cudaGetSymbolAddress((void**)&AS, g_AS);
    cudaGetSymbolAddress((void**)&AD, g_AD);
    cudaGetSymbolAddress((void**)&ASP, g_ASP);
    cudaGetSymbolAddress((void**)&ADP, g_ADP);
    cudaGetSymbolAddress((void**)&QKVH, g_QKVH);
    cudaGetSymbolAddress((void**)&WQKVH, g_WQKVH);
    cudaGetSymbolAddress((void**)&BQKV, g_BQKV);
    cudaGetSymbolAddress((void**)&GATWH, g_GATWH);
    cudaGetSymbolAddress((void**)&WOH, g_WOH);
    cudaGetSymbolAddress((void**)&W1H, g_W1H);
    cudaGetSymbolAddress((void**)&W2H, g_W2H);
    cudaGetSymbolAddress((void**)&AOH, g_AOH);
    cudaGetSymbolAddress((void**)&Y,  g_Y);
    cudaGetSymbolAddress((void**)&YH, g_YH);
    cudaGetSymbolAddress((void**)&FFH, g_FFH);
    cudaGetSymbolAddress((void**)&BITS, g_BITS);
    cudaGetSymbolAddress((void**)&NBR, g_NBR);
    cudaGetSymbolAddress((void**)&CNT, g_CNT);

    const int M = MTOT;

    pack_adj_k<<<(BB*32*NNODE)/256, 256>>>(mask, BITS);
    build_nbr_k<<<(MTOT)/256, 256>>>(BITS, NBR, CNT);
    pack_qkv_k<<<(LTN*DD*3*DD + 255)/256, 256>>>(Wq, Wk, Wv, bq, bk, bv, WQKVH, BQKV);
    cvt_half_k<<<(MTOT*DD/4 + 255)/256, 256>>>(emb, EMBH, MTOT*DD);
    cvt_half_k<<<(LGN*HH*DD*DD/4 + 255)/256, 256>>>(gatW, GATWH, LGN*HH*DD*DD);
    cvt_half_k<<<(LTN*DD*DD/4 + 255)/256, 256>>>(Wo, WOH, LTN*DD*DD);
    cvt_half_k<<<(LTN*DD*DFFX/4 + 255)/256, 256>>>(W1, W1H, LTN*DD*DFFX);
    cvt_half_k<<<(LTN*DFFX*DD/4 + 255)/256, 256>>>(W2, W2H, LTN*DFFX*DD);

    // ---- GAT stack ----
    const __half* x = EMBH;
    for (int l = 0; l < LGN; l++) {
        hgemm_k<true,0,1,1><<<dim3((HH*DD)/128, M/128), 256>>>(
            M, HH*DD, DD, x, DD, GATWH + (size_t)l*HH*DD*DD, DD,
            HBH, HH*DD, nullptr, attS + l*HH*DD, attD + l*HH*DD, ASP, ADP);
        asad_reduce_k<<<(MTOT*8)/256, 256>>>(ASP, ADP, AS, AD);
        quant_h_k<<<MTOT, 256>>>(HBH, HQ, HS);
        gat_agg_k<<<M, 256>>>(HQ, HS, AS, AD, NBR, CNT, gatB + l*DD, Y, YH);
        x = YH;
    }
    ln_warp_k<1,1><<<M/8, 256>>>(emb, Y, glnS, glnB, XC, XCH);

    // ---- transformer layers ----
    for (int l = 0; l < LTN; l++) {
        hgemm_k<false,0,1,0><<<dim3((3*DD)/128, M/128), 256>>>(
            M, 3*DD, DD, XCH, DD, WQKVH + (size_t)l*DD*3*DD, 3*DD, QKVH, 3*DD,
            BQKV + l*3*DD, nullptr, nullptr, nullptr, nullptr);
        attn_sparse_k<<<M, 256>>>(QKVH, NBR, CNT, AOH);
        hgemm_k<false,0,0,0><<<dim3(DD/128, M/128), 256>>>(
            M, DD, DD, AOH, DD, WOH + (size_t)l*DD*DD, DD, Y, DD,
            bo + l*DD, nullptr, nullptr, nullptr, nullptr);
        ln_warp_k<0,1><<<M/8, 256>>>(XC, Y, l1s + l*DD, l1b + l*DD, XC, XCH);
        hgemm_k<false,1,1,0><<<dim3(DFFX/128, M/128), 256>>>(
            M, DFFX, DD, XCH, DD, W1H + (size_t)l*DD*DFFX, DFFX, FFH, DFFX,
            b1 + l*DFFX, nullptr, nullptr, nullptr, nullptr);
        hgemm_k<false,0,0,0><<<dim3(DD/128, M/128), 256>>>(
            M, DD, DFFX, FFH, DFFX, W2H + (size_t)l*DFFX*DD, DD, Y, DD,
            b2 + l*DD, nullptr, nullptr, nullptr, nullptr);
        if (l == LTN - 1)
            ln_warp_k<0,0><<<M/8, 256>>>(XC, Y, l2s + l*DD, l2b + l*DD, out, nullptr);
        else
            ln_warp_k<0,1><<<M/8, 256>>>(XC, Y, l2s + l*DD, l2b + l*DD, XC, XCH);
    }
}

// round 10
// speedup vs baseline: 1.2094x; 1.2094x over previous
#include <cuda_runtime.h>
#include <cuda_fp16.h>
#include <math.h>

// ---------------- dims ----------------
#define BB    8
#define NNODE 1024
#define DD    256
#define HH    8
#define DHH   32
#define DFFX  1024
#define LGN   2
#define LTN   2
#define NBCAP 256
#define MTOT  (BB*NNODE)

// ---------------- scratch (device globals; no runtime allocation) ----------------
__device__ float                 g_XC[MTOT*DD];
__device__ __align__(16) __half  g_XCH[MTOT*DD];
__device__ __align__(16) __half  g_EMBH[MTOT*DD];
__device__ __align__(16) __half  g_HBH[MTOT*HH*DD];
__device__ float                 g_AS[MTOT*HH];
__device__ float                 g_AD[MTOT*HH];
__device__ float                 g_ASP[32*MTOT];
__device__ float                 g_ADP[32*MTOT];
__device__ __align__(16) __half  g_QKVH[MTOT*3*DD];
__device__ __align__(16) __half  g_WQKVH[LTN*DD*3*DD];
__device__ float                 g_BQKV[LTN*3*DD];
__device__ __align__(16) __half  g_GATWH[LGN*HH*DD*DD];
__device__ __align__(16) __half  g_WOH[LTN*DD*DD];
__device__ __align__(16) __half  g_W1H[LTN*DD*DFFX];
__device__ __align__(16) __half  g_W2H[LTN*DFFX*DD];
__device__ __align__(16) __half  g_AOH[MTOT*DD];
__device__ float                 g_Y [MTOT*DD];
__device__ __align__(16) __half  g_YH[MTOT*DD];
__device__ __align__(16) __half  g_FFH[MTOT*DFFX];
__device__ unsigned              g_BITS[MTOT*(NNODE/32)];
__device__ int                   g_NBR[MTOT*NBCAP];
__device__ int                   g_CNT[MTOT];

// ---------------- helpers ----------------
__device__ __forceinline__ void mma_f16(float* c, const unsigned* a, const unsigned* b) {
    asm volatile(
        "mma.sync.aligned.m16n8k16.row.col.f32.f16.f16.f32 "
        "{%0,%1,%2,%3}, {%4,%5,%6,%7}, {%8,%9}, {%0,%1,%2,%3};\n"
        : "+f"(c[0]), "+f"(c[1]), "+f"(c[2]), "+f"(c[3])
        : "r"(a[0]), "r"(a[1]), "r"(a[2]), "r"(a[3]), "r"(b[0]), "r"(b[1]));
}

__device__ __forceinline__ unsigned saddr(const void* p) {
    return (unsigned)__cvta_generic_to_shared(p);
}
__device__ __forceinline__ void cp16(unsigned dst, const void* src) {
    asm volatile("cp.async.cg.shared.global [%0], [%1], 16;\n" :: "r"(dst), "l"(src));
}
__device__ __forceinline__ void cp_commit() {
    asm volatile("cp.async.commit_group;\n" ::: "memory");
}
template<int N>
__device__ __forceinline__ void cp_wait() {
    asm volatile("cp.async.wait_group %0;\n" :: "n"(N) : "memory");
}
__device__ __forceinline__ void ldsm4(unsigned& r0, unsigned& r1, unsigned& r2, unsigned& r3,
                                      unsigned addr) {
    asm volatile("ldmatrix.sync.aligned.m8n8.x4.shared.b16 {%0,%1,%2,%3}, [%4];"
                 : "=r"(r0), "=r"(r1), "=r"(r2), "=r"(r3) : "r"(addr));
}
__device__ __forceinline__ void ldsm4t(unsigned& r0, unsigned& r1, unsigned& r2, unsigned& r3,
                                       unsigned addr) {
    asm volatile("ldmatrix.sync.aligned.m8n8.x4.trans.shared.b16 {%0,%1,%2,%3}, [%4];"
                 : "=r"(r0), "=r"(r1), "=r"(r2), "=r"(r3) : "r"(addr));
}

// ---------------- adjacency pack ----------------
__global__ void pack_adj_k(const int* __restrict__ mask, unsigned* __restrict__ bits) {
    int idx = blockIdx.x * blockDim.x + threadIdx.x;
    int t  = idx & (NNODE - 1);
    int sw = (idx >> 10) & 31;
    int b  = idx >> 15;
    const int* mp = mask + ((size_t)b * NNODE + (size_t)sw * 32) * NNODE + t;
    unsigned w = 0;
    #pragma unroll
    for (int i = 0; i < 32; i++)
        if (mp[(size_t)i * NNODE] > 0) w |= (1u << i);
    int s0 = sw * 32;
    if (t >= s0 && t < s0 + 32) w |= (1u << (t - s0));
    bits[(b * NNODE + t) * 32 + sw] = w;
}

// ---------------- neighbor list build ----------------
__global__ void build_nbr_k(const unsigned* __restrict__ bits,
                            int* __restrict__ nbr, int* __restrict__ cnt) {
    int bt = blockIdx.x * blockDim.x + threadIdx.x;
    if (bt >= MTOT) return;
    const unsigned* bw = bits + (size_t)bt * 32;
    int* np = nbr + (size_t)bt * NBCAP;
    int c = 0;
    #pragma unroll 4
    for (int w = 0; w < 32; w++) {
        unsigned m = bw[w];
        while (m) {
            int bit = __ffs(m) - 1;
            m &= m - 1;
            if (c < NBCAP) np[c] = w * 32 + bit;
            c++;
        }
    }
    cnt[bt] = c < NBCAP ? c : NBCAP;
}

// ---------------- generic fp32 -> fp16 convert ----------------
__global__ void cvt_half_k(const float* __restrict__ src, __half* __restrict__ dst, int n) {
    int i = blockIdx.x * 256 + threadIdx.x;
    if (i * 4 >= n) return;
    float4 v = *(const float4*)(src + i * 4);
    *(__half2*)(dst + i * 4)     = __floats2half2_rn(v.x, v.y);
    *(__half2*)(dst + i * 4 + 2) = __floats2half2_rn(v.z, v.w);
}

// ---------------- QKV pack ----------------
__global__ void pack_qkv_k(const float* __restrict__ Wq, const float* __restrict__ Wk,
                           const float* __restrict__ Wv, const float* __restrict__ bq,
                           const float* __restrict__ bk, const float* __restrict__ bv,
                           __half* __restrict__ W, float* __restrict__ Bb)
{
    int idx = blockIdx.x * 256 + threadIdx.x;
    if (idx >= LTN * DD * 3 * DD) return;
    int n = idx % (3 * DD);
    int k = (idx / (3 * DD)) % DD;
    int l = idx / (3 * DD * DD);
    float v;
    if (n < DD)            v = Wq[((size_t)l * DD + k) * DD + n];
    else if (n < 2 * DD)   v = Wk[((size_t)l * DD + k) * DD + n - DD];
    else                   v = Wv[((size_t)l * DD + k) * DD + n - 2 * DD];
    W[idx] = __float2half_rn(v);
    if (k == 0) {
        float bvv;
        if (n < DD)          bvv = bq[l * DD + n];
        else if (n < 2 * DD) bvv = bk[l * DD + n - DD];
        else                 bvv = bv[l * DD + n - 2 * DD];
        Bb[l * 3 * DD + n] = bvv;
    }
}

// ---------------- fp16 tensor-core GEMM: 3-stage cp.async + ldmatrix ----------------
// One __syncthreads per k-tile: prefetch t+2 targets buffer (t+2)%3 == (t-1)%3,
// freed by the same barrier that publishes tile t.
template<bool BT, int ACT, int HALF_OUT, int ASAD>
__global__ void __launch_bounds__(256) hgemm_k(
    int M, int Ncol, int K,
    const __half* __restrict__ A, int lda,
    const __half* __restrict__ B, int ldb,
    void* __restrict__ Cv, int ldc,
    const float* __restrict__ bias,
    const float* __restrict__ attS, const float* __restrict__ attD,
    float* __restrict__ ASP, float* __restrict__ ADP)
{
    __shared__ __align__(16) __half sA[3][128 * 24];
    __shared__ __align__(16) __half sB[3][3072];
    const int tid  = threadIdx.x;
    const int lane = tid & 31, wid = tid >> 5;
    const int wm = wid & 3, wn = wid >> 2;
    const int m0 = blockIdx.y * 128, n0 = blockIdx.x * 128;
    const int r = lane >> 2, cq = lane & 3;

    float acc[2][8][4];
    #pragma unroll
    for (int mt = 0; mt < 2; mt++)
        #pragma unroll
        for (int nt = 0; nt < 8; nt++)
            #pragma unroll
            for (int u = 0; u < 4; u++) acc[mt][nt][u] = 0.f;

    const int T = K / 16;

    auto loadT = [&](int st, int k0) {
        {
            int m = tid >> 1, c = tid & 1;
            cp16(saddr(&sA[st][m * 24 + c * 8]), A + (size_t)(m0 + m) * lda + k0 + c * 8);
        }
        if (BT) {
            int n = tid >> 1, c = tid & 1;
            cp16(saddr(&sB[st][n * 24 + c * 8]), B + (size_t)(n0 + n) * ldb + k0 + c * 8);
        } else {
            int kk = tid >> 4, c = tid & 15;
            cp16(saddr(&sB[st][kk * 136 + c * 8]), B + (size_t)(k0 + kk) * ldb + n0 + c * 8);
        }
        cp_commit();
    };

    loadT(0, 0);
    loadT(1, 16);
    for (int t = 0; t < T; t++) {
        if (t + 1 < T) cp_wait<1>(); else cp_wait<0>();
        __syncthreads();
        if (t + 2 < T) loadT((t + 2) % 3, (t + 2) * 16);
        const int st = t % 3;

        unsigned af[2][4], bf[8][2];
        #pragma unroll
        for (int mt = 0; mt < 2; mt++) {
            int mrow = wm * 32 + mt * 16;
            unsigned addr = saddr(&sA[st][(mrow + (lane & 15)) * 24 + (lane >> 4) * 8]);
            ldsm4(af[mt][0], af[mt][1], af[mt][2], af[mt][3], addr);
        }
        #pragma unroll
        for (int p = 0; p < 4; p++) {
            int nb = wn * 64 + p * 16;
            if (BT) {
                int row = nb + (lane & 7) + ((lane >> 4) << 3);
                int col = ((lane >> 3) & 1) * 8;
                unsigned addr = saddr(&sB[st][row * 24 + col]);
                ldsm4(bf[2 * p][0], bf[2 * p][1], bf[2 * p + 1][0], bf[2 * p + 1][1], addr);
            } else {
                int krow = (lane & 7) + (((lane >> 3) & 1) << 3);
                int coln = nb + (lane >> 4) * 8;
                unsigned addr = saddr(&sB[st][krow * 136 + coln]);
                ldsm4t(bf[2 * p][0], bf[2 * p][1], bf[2 * p + 1][0], bf[2 * p + 1][1], addr);
            }
        }
        #pragma unroll
        for (int mt = 0; mt < 2; mt++)
            #pragma unroll
            for (int nt = 0; nt < 8; nt++)
                mma_f16(acc[mt][nt], af[mt], bf[nt]);
    }

    if (ASAD) {
        float sS[2][2] = {{0,0},{0,0}}, sD[2][2] = {{0,0},{0,0}};
        #pragma unroll
        for (int mt = 0; mt < 2; mt++)
            #pragma unroll
            for (int nt = 0; nt < 8; nt++)
                #pragma unroll
                for (int u = 0; u < 4; u++) {
                    int g = n0 + wn * 64 + nt * 8 + cq * 2 + (u & 1);
                    float v = acc[mt][nt][u];
                    sS[mt][u >> 1] += v * attS[g];
                    sD[mt][u >> 1] += v * attD[g];
                }
        #pragma unroll
        for (int o = 1; o <= 2; o <<= 1)
            #pragma unroll
            for (int mt = 0; mt < 2; mt++)
                #pragma unroll
                for (int q = 0; q < 2; q++) {
                    sS[mt][q] += __shfl_xor_sync(0xffffffffu, sS[mt][q], o);
                    sD[mt][q] += __shfl_xor_sync(0xffffffffu, sD[mt][q], o);
                }
        if (cq == 0) {
            int j = (n0 >> 6) + wn;
            #pragma unroll
            for (int mt = 0; mt < 2; mt++)
                #pragma unroll
                for (int q = 0; q < 2; q++) {
                    int row = m0 + wm * 32 + mt * 16 + r + q * 8;
                    ASP[(size_t)j * M + row] = sS[mt][q];
                    ADP[(size_t)j * M + row] = sD[mt][q];
                }
        }
    }

    #pragma unroll
    for (int mt = 0; mt < 2; mt++) {
        int mrow = m0 + wm * 32 + mt * 16 + r;
        #pragma unroll
        for (int nt = 0; nt < 8; nt++) {
            int ncol = n0 + wn * 64 + nt * 8 + cq * 2;
            float* ac = acc[mt][nt];
            float2 v0 = make_float2(ac[0], ac[1]);
            float2 v1 = make_float2(ac[2], ac[3]);
            if (bias) {
                float b0 = bias[ncol], b1 = bias[ncol + 1];
                v0.x += b0; v0.y += b1; v1.x += b0; v1.y += b1;
            }
            if (ACT == 1) {
                v0.x = fmaxf(v0.x, 0.f); v0.y = fmaxf(v0.y, 0.f);
                v1.x = fmaxf(v1.x, 0.f); v1.y = fmaxf(v1.y, 0.f);
            }
            if (HALF_OUT) {
                __half* Ch = (__half*)Cv;
                *(__half2*)(Ch + (size_t)mrow * ldc + ncol) = __floats2half2_rn(v0.x, v0.y);
                *(__half2*)(Ch + (size_t)(mrow + 8) * ldc + ncol) = __floats2half2_rn(v1.x, v1.y);
            } else {
                float* Cf = (float*)Cv;
                *(float2*)(Cf + (size_t)mrow * ldc + ncol) = v0;
                *(float2*)(Cf + (size_t)(mrow + 8) * ldc + ncol) = v1;
            }
        }
    }
}

// ---------------- asad reduce ----------------
__global__ void asad_reduce_k(const float* __restrict__ ASP, const float* __restrict__ ADP,
                              float* __restrict__ as_, float* __restrict__ ad_)
{
    int idx = blockIdx.x * 256 + threadIdx.x;
    int row = idx >> 3, h = idx & 7;
    float s = 0.f, d = 0.f;
    #pragma unroll
    for (int j = 4 * h; j < 4 * h + 4; j++) {
        s += ASP[(size_t)j * MTOT + row];
        d += ADP[(size_t)j * MTOT + row];
    }
    as_[row * 8 + h] = s;
    ad_[row * 8 + h] = d;
}

// ---------------- sparse GAT aggregation (fp16; warp = head, lane = 8 cols) ----------------
__global__ void __launch_bounds__(256) gat_agg_k(
    const __half* __restrict__ hb, const float* __restrict__ as_,
    const float* __restrict__ ad_, const int* __restrict__ nbr,
    const int* __restrict__ cnt, const float* __restrict__ bias,
    float* __restrict__ y, __half* __restrict__ yh)
{
    __shared__ int   s_nbr[NBCAP];
    __shared__ float s_alpha[HH][NBCAP];
    __shared__ float s_inv[HH];
    __shared__ float s_red[HH][DD];
    int bt  = blockIdx.x;
    int b   = bt >> 10;
    int tid = threadIdx.x;
    int nc  = cnt[bt];
    for (int j = tid; j < nc; j += 256) s_nbr[j] = nbr[(size_t)bt * NBCAP + j];
    __syncthreads();

    for (int j = tid; j < nc; j += 256) {
        int s = s_nbr[j];
        const float* ap = as_ + (size_t)(b * NNODE + s) * HH;
        #pragma unroll
        for (int h = 0; h < HH; h++) {
            float e = ad_[bt * HH + h] + ap[h];
            e = e >= 0.f ? e : 0.2f * e;
            s_alpha[h][j] = __expf(e);
        }
    }
    __syncthreads();

    int h    = tid >> 5;
    int lane = tid & 31;
    {
        float sum = 0.f;
        for (int j = lane; j < nc; j += 32) sum += s_alpha[h][j];
        #pragma unroll
        for (int o = 16; o; o >>= 1) sum += __shfl_xor_sync(0xffffffffu, sum, o);
        if (lane == 0) s_inv[h] = 1.f / (8.f * sum);
    }
    __syncthreads();
    for (int j = tid; j < nc; j += 256) {
        #pragma unroll
        for (int hh = 0; hh < HH; hh++) s_alpha[hh][j] *= s_inv[hh];
    }
    __syncthreads();

    const __half* hbase = hb + (size_t)b * NNODE * (HH * DD) + h * DD + lane * 8;
    float a[8];
    #pragma unroll
    for (int i = 0; i < 8; i++) a[i] = 0.f;
    #pragma unroll 2
    for (int j = 0; j < nc; j++) {
        float w = s_alpha[h][j];
        const float4* p = (const float4*)(hbase + (size_t)s_nbr[j] * (HH * DD));
        float4 raw = *p;
        const __half2* h2 = (const __half2*)&raw;
        #pragma unroll
        for (int i = 0; i < 4; i++) {
            float2 u = __half22float2(h2[i]);
            a[2 * i]     = fmaf(w, u.x, a[2 * i]);
            a[2 * i + 1] = fmaf(w, u.y, a[2 * i + 1]);
        }
    }
    #pragma unroll
    for (int i = 0; i < 8; i += 4)
        *(float4*)&s_red[h][lane * 8 + i] = make_float4(a[i], a[i+1], a[i+2], a[i+3]);
    __syncthreads();

    {
        int c = tid;
        float v = bias[c];
        #pragma unroll
        for (int hh = 0; hh < HH; hh++) v += s_red[hh][c];
        y[(size_t)bt * DD + c] = v;
        yh[(size_t)bt * DD + c] = __float2half_rn(v);
    }
}

// ---------------- sparse masked attention (fp16 QKV) ----------------
__global__ void __launch_bounds__(256) attn_sparse_k(
    const __half* __restrict__ QKV, const int* __restrict__ nbr,
    const int* __restrict__ cnt, __half* __restrict__ Om)
{
    __shared__ int s_nbr[NBCAP];
    int bt  = blockIdx.x;
    int b   = bt >> 10;
    int tid = threadIdx.x;
    int nc  = cnt[bt];
    for (int j = tid; j < nc; j += 256) s_nbr[j] = nbr[(size_t)bt * NBCAP + j];
    __syncthreads();
    int h = tid >> 5, lane = tid & 31;
    const int LD3 = 3 * DD;
    float q = __half2float(QKV[(size_t)bt * LD3 + h * DHH + lane]) * 0.17677669529663687f;
    float accv = 0.f, accw = 0.f;
    int j = 0;
    for (; j + 4 <= nc; j += 4) {
        float d[4], vv[4];
        #pragma unroll
        for (int u = 0; u < 4; u++) {
            int s = s_nbr[j + u];
            size_t base = (size_t)(b * NNODE + s) * LD3 + h * DHH + lane;
            d[u]  = q * __half2float(QKV[base + DD]);
            vv[u] = __half2float(QKV[base + 2 * DD]);
        }
        #pragma unroll
        for (int o = 16; o; o >>= 1) {
            #pragma unroll
            for (int u = 0; u < 4; u++) d[u] += __shfl_xor_sync(0xffffffffu, d[u], o);
        }
        #pragma unroll
        for (int u = 0; u < 4; u++) {
            float w = __expf(d[u]);
            accv = fmaf(w, vv[u], accv);
            accw += w;
        }
    }
    for (; j < nc; j++) {
        int s = s_nbr[j];
        size_t base = (size_t)(b * NNODE + s) * LD3 + h * DHH + lane;
        float d = q * __half2float(QKV[base + DD]);
        float vvv = __half2float(QKV[base + 2 * DD]);
        #pragma unroll
        for (int o = 16; o; o >>= 1) d += __shfl_xor_sync(0xffffffffu, d, o);
        float w = __expf(d);
        accv = fmaf(w, vvv, accv);
        accw += w;
    }
    Om[(size_t)bt * DD + h * DHH + lane] = __float2half_rn(accv / accw);
}

// ---------------- layernorm: warp per row ----------------
template<int MODE, int WRITEH>
__global__ void __launch_bounds__(256) ln_warp_k(
    const float* __restrict__ a, const float* __restrict__ bsrc,
    const float* __restrict__ gam, const float* __restrict__ bet,
    float* __restrict__ out, __half* __restrict__ outh)
{
    int row  = blockIdx.x * 8 + (threadIdx.x >> 5);
    int lane = threadIdx.x & 31;
    size_t base = (size_t)row * DD;
    float v[8];
    float sum = 0.f;
    #pragma unroll
    for (int p = 0; p < 2; p++) {
        int c = lane * 4 + p * 128;
        float4 av = *(const float4*)(a + base + c);
        float4 bv = *(const float4*)(bsrc + base + c);
        if (MODE == 1) {
            bv.x = fmaxf(bv.x, 0.f); bv.y = fmaxf(bv.y, 0.f);
            bv.z = fmaxf(bv.z, 0.f); bv.w = fmaxf(bv.w, 0.f);
        }
        v[p*4+0] = av.x + bv.x; v[p*4+1] = av.y + bv.y;
        v[p*4+2] = av.z + bv.z; v[p*4+3] = av.w + bv.w;
        sum += v[p*4+0] + v[p*4+1] + v[p*4+2] + v[p*4+3];
    }
    #pragma unroll
    for (int o = 16; o; o >>= 1) sum += __shfl_xor_sync(0xffffffffu, sum, o);
    float mean = sum * (1.f / DD);
    float var = 0.f;
    #pragma unroll
    for (int i = 0; i < 8; i++) { float d = v[i] - mean; var += d * d; }
    #pragma unroll
    for (int o = 16; o; o >>= 1) var += __shfl_xor_sync(0xffffffffu, var, o);
    float rstd = rsqrtf(var * (1.f / DD) + 1e-5f);
    #pragma unroll
    for (int p = 0; p < 2; p++) {
        int c = lane * 4 + p * 128;
        float4 g = *(const float4*)(gam + c);
        float4 bb = *(const float4*)(bet + c);
        float4 o4;
        o4.x = (v[p*4+0] - mean) * rstd * g.x + bb.x;
        o4.y = (v[p*4+1] - mean) * rstd * g.y + bb.y;
        o4.z = (v[p*4+2] - mean) * rstd * g.z + bb.z;
        o4.w = (v[p*4+3] - mean) * rstd * g.w + bb.w;
        *(float4*)(out + base + c) = o4;
        if (WRITEH) {
            __half2 h0 = __floats2half2_rn(o4.x, o4.y);
            __half2 h1 = __floats2half2_rn(o4.z, o4.w);
            *(uint2*)(outh + base + c) = make_uint2(*(unsigned*)&h0, *(unsigned*)&h1);
        }
    }
}

extern "C" void kernel_launch(void* const* d_in, const int* in_sizes, int n_in,
                              void* d_out, int out_size)
{
    const float* emb  = (const float*)d_in[0];
    const int*   mask = (const int*)  d_in[2];
    const float* gatW = (const float*)d_in[4];
    const float* attS = (const float*)d_in[5];
    const float* attD = (const float*)d_in[6];
    const float* gatB = (const float*)d_in[7];
    const float* glnS = (const float*)d_in[8];
    const float* glnB = (const float*)d_in[9];
    const float* Wq = (const float*)d_in[10], *bq = (const float*)d_in[11];
    const float* Wk = (const float*)d_in[12], *bk = (const float*)d_in[13];
    const float* Wv = (const float*)d_in[14], *bv = (const float*)d_in[15];
    const float* Wo = (const float*)d_in[16], *bo = (const float*)d_in[17];
    const float* W1 = (const float*)d_in[18], *b1 = (const float*)d_in[19];
    const float* W2 = (const float*)d_in[20], *b2 = (const float*)d_in[21];
    const float* l1s = (const float*)d_in[22], *l1b = (const float*)d_in[23];
    const float* l2s = (const float*)d_in[24], *l2b = (const float*)d_in[25];
    float* out = (float*)d_out;

    float *XC,*AS,*AD,*ASP,*ADP,*BQKV,*Y;
    __half *XCH,*EMBH,*HBH,*QKVH,*WQKVH,*GATWH,*WOH,*W1H,*W2H,*AOH,*YH,*FFH;
    unsigned* BITS; int *NBR,*CNT;
    cudaGetSymbolAddress((void**)&XC, g_XC);
    cudaGetSymbolAddress((void**)&XCH, g_XCH);
    cudaGetSymbolAddress((void**)&EMBH, g_EMBH);
    cudaGetSymbolAddress((void**)&HBH, g_HBH);
    cudaGetSymbolAddress((void**)&AS, g_AS);
    cudaGetSymbolAddress((void**)&AD, g_AD);
    cudaGetSymbolAddress((void**)&ASP, g_ASP);
    cudaGetSymbolAddress((void**)&ADP, g_ADP);
    cudaGetSymbolAddress((void**)&QKVH, g_QKVH);
    cudaGetSymbolAddress((void**)&WQKVH, g_WQKVH);
    cudaGetSymbolAddress((void**)&BQKV, g_BQKV);
    cudaGetSymbolAddress((void**)&GATWH, g_GATWH);
    cudaGetSymbolAddress((void**)&WOH, g_WOH);
    cudaGetSymbolAddress((void**)&W1H, g_W1H);
    cudaGetSymbolAddress((void**)&W2H, g_W2H);
    cudaGetSymbolAddress((void**)&AOH, g_AOH);
    cudaGetSymbolAddress((void**)&Y,  g_Y);
    cudaGetSymbolAddress((void**)&YH, g_YH);
    cudaGetSymbolAddress((void**)&FFH, g_FFH);
    cudaGetSymbolAddress((void**)&BITS, g_BITS);
    cudaGetSymbolAddress((void**)&NBR, g_NBR);
    cudaGetSymbolAddress((void**)&CNT, g_CNT);

    const int M = MTOT;

    pack_adj_k<<<(BB*32*NNODE)/256, 256>>>(mask, BITS);
    build_nbr_k<<<(MTOT)/256, 256>>>(BITS, NBR, CNT);
    pack_qkv_k<<<(LTN*DD*3*DD + 255)/256, 256>>>(Wq, Wk, Wv, bq, bk, bv, WQKVH, BQKV);
    cvt_half_k<<<(MTOT*DD/4 + 255)/256, 256>>>(emb, EMBH, MTOT*DD);
    cvt_half_k<<<(LGN*HH*DD*DD/4 + 255)/256, 256>>>(gatW, GATWH, LGN*HH*DD*DD);
    cvt_half_k<<<(LTN*DD*DD/4 + 255)/256, 256>>>(Wo, WOH, LTN*DD*DD);
    cvt_half_k<<<(LTN*DD*DFFX/4 + 255)/256, 256>>>(W1, W1H, LTN*DD*DFFX);
    cvt_half_k<<<(LTN*DFFX*DD/4 + 255)/256, 256>>>(W2, W2H, LTN*DFFX*DD);

    // ---- GAT stack ----
    const __half* x = EMBH;
    for (int l = 0; l < LGN; l++) {
        hgemm_k<true,0,1,1><<<dim3((HH*DD)/128, M/128), 256>>>(
            M, HH*DD, DD, x, DD, GATWH + (size_t)l*HH*DD*DD, DD,
            HBH, HH*DD, nullptr, attS + l*HH*DD, attD + l*HH*DD, ASP, ADP);
        asad_reduce_k<<<(MTOT*8)/256, 256>>>(ASP, ADP, AS, AD);
        gat_agg_k<<<M, 256>>>(HBH, AS, AD, NBR, CNT, gatB + l*DD, Y, YH);
        x = YH;
    }
    ln_warp_k<1,1><<<M/8, 256>>>(emb, Y, glnS, glnB, XC, XCH);

    // ---- transformer layers ----
    for (int l = 0; l < LTN; l++) {
        hgemm_k<false,0,1,0><<<dim3((3*DD)/128, M/128), 256>>>(
            M, 3*DD, DD, XCH, DD, WQKVH + (size_t)l*DD*3*DD, 3*DD, QKVH, 3*DD,
            BQKV + l*3*DD, nullptr, nullptr, nullptr, nullptr);
        attn_sparse_k<<<M, 256>>>(QKVH, NBR, CNT, AOH);
        hgemm_k<false,0,0,0><<<dim3(DD/128, M/128), 256>>>(
            M, DD, DD, AOH, DD, WOH + (size_t)l*DD*DD, DD, Y, DD,
            bo + l*DD, nullptr, nullptr, nullptr, nullptr);
        ln_warp_k<0,1><<<M/8, 256>>>(XC, Y, l1s + l*DD, l1b + l*DD, XC, XCH);
        hgemm_k<false,1,1,0><<<dim3(DFFX/128, M/128), 256>>>(
            M, DFFX, DD, XCH, DD, W1H + (size_t)l*DD*DFFX, DFFX, FFH, DFFX,
            b1 + l*DFFX, nullptr, nullptr, nullptr, nullptr);
        hgemm_k<false,0,0,0><<<dim3(DD/128, M/128), 256>>>(
            M, DD, DFFX, FFH, DFFX, W2H + (size_t)l*DFFX*DD, DD, Y, DD,
            b2 + l*DD, nullptr, nullptr, nullptr, nullptr);
        if (l == LTN - 1)
            ln_warp_k<0,0><<<M/8, 256>>>(XC, Y, l2s + l*DD, l2b + l*DD, out, nullptr);
        else
            ln_warp_k<0,1><<<M/8, 256>>>(XC, Y, l2s + l*DD, l2b + l*DD, XC, XCH);
    }
}

// round 11
// speedup vs baseline: 1.2772x; 1.0561x over previous
#include <cuda_runtime.h>
#include <cuda_fp16.h>
#include <math.h>

// ---------------- dims ----------------
#define BB    8
#define NNODE 1024
#define DD    256
#define HH    8
#define DHH   32
#define DFFX  1024
#define LGN   2
#define LTN   2
#define NBCAP 256
#define MTOT  (BB*NNODE)

// ---------------- scratch (device globals; no runtime allocation) ----------------
__device__ float                 g_XC[MTOT*DD];
__device__ __align__(16) __half  g_XCH[MTOT*DD];
__device__ __align__(16) __half  g_EMBH[MTOT*DD];
__device__ __align__(16) __half  g_HBH[MTOT*HH*DD];
__device__ float                 g_AS[MTOT*HH];
__device__ float                 g_AD[MTOT*HH];
__device__ float                 g_ASP[32*MTOT];
__device__ float                 g_ADP[32*MTOT];
__device__ __align__(16) __half  g_QKVH[MTOT*3*DD];
__device__ __align__(16) __half  g_WQKVH[LTN*DD*3*DD];
__device__ float                 g_BQKV[LTN*3*DD];
__device__ __align__(16) __half  g_GATWH[LGN*HH*DD*DD];
__device__ __align__(16) __half  g_WOH[LTN*DD*DD];
__device__ __align__(16) __half  g_W1H[LTN*DD*DFFX];
__device__ __align__(16) __half  g_W2H[LTN*DFFX*DD];
__device__ __align__(16) __half  g_AOH[MTOT*DD];
__device__ float                 g_Y [MTOT*DD];
__device__ __align__(16) __half  g_YH[MTOT*DD];
__device__ __align__(16) __half  g_FFH[MTOT*DFFX];
__device__ unsigned              g_BITS[MTOT*(NNODE/32)];
__device__ int                   g_NBR[MTOT*NBCAP];
__device__ int                   g_CNT[MTOT];

// ---------------- helpers ----------------
__device__ __forceinline__ void mma_f16(float* c, const unsigned* a, const unsigned* b) {
    asm volatile(
        "mma.sync.aligned.m16n8k16.row.col.f32.f16.f16.f32 "
        "{%0,%1,%2,%3}, {%4,%5,%6,%7}, {%8,%9}, {%0,%1,%2,%3};\n"
        : "+f"(c[0]), "+f"(c[1]), "+f"(c[2]), "+f"(c[3])
        : "r"(a[0]), "r"(a[1]), "r"(a[2]), "r"(a[3]), "r"(b[0]), "r"(b[1]));
}

__device__ __forceinline__ unsigned saddr(const void* p) {
    return (unsigned)__cvta_generic_to_shared(p);
}
__device__ __forceinline__ void cp16(unsigned dst, const void* src) {
    asm volatile("cp.async.cg.shared.global [%0], [%1], 16;\n" :: "r"(dst), "l"(src));
}
__device__ __forceinline__ void cp_commit() {
    asm volatile("cp.async.commit_group;\n" ::: "memory");
}
template<int N>
__device__ __forceinline__ void cp_wait() {
    asm volatile("cp.async.wait_group %0;\n" :: "n"(N) : "memory");
}
__device__ __forceinline__ void ldsm4(unsigned& r0, unsigned& r1, unsigned& r2, unsigned& r3,
                                      unsigned addr) {
    asm volatile("ldmatrix.sync.aligned.m8n8.x4.shared.b16 {%0,%1,%2,%3}, [%4];"
                 : "=r"(r0), "=r"(r1), "=r"(r2), "=r"(r3) : "r"(addr));
}
__device__ __forceinline__ void ldsm4t(unsigned& r0, unsigned& r1, unsigned& r2, unsigned& r3,
                                       unsigned addr) {
    asm volatile("ldmatrix.sync.aligned.m8n8.x4.trans.shared.b16 {%0,%1,%2,%3}, [%4];"
                 : "=r"(r0), "=r"(r1), "=r"(r2), "=r"(r3) : "r"(addr));
}

// ---------------- adjacency pack ----------------
__global__ void pack_adj_k(const int* __restrict__ mask, unsigned* __restrict__ bits) {
    int idx = blockIdx.x * blockDim.x + threadIdx.x;
    int t  = idx & (NNODE - 1);
    int sw = (idx >> 10) & 31;
    int b  = idx >> 15;
    const int* mp = mask + ((size_t)b * NNODE + (size_t)sw * 32) * NNODE + t;
    unsigned w = 0;
    #pragma unroll
    for (int i = 0; i < 32; i++)
        if (mp[(size_t)i * NNODE] > 0) w |= (1u << i);
    int s0 = sw * 32;
    if (t >= s0 && t < s0 + 32) w |= (1u << (t - s0));
    bits[(b * NNODE + t) * 32 + sw] = w;
}

// ---------------- neighbor list build ----------------
__global__ void build_nbr_k(const unsigned* __restrict__ bits,
                            int* __restrict__ nbr, int* __restrict__ cnt) {
    int bt = blockIdx.x * blockDim.x + threadIdx.x;
    if (bt >= MTOT) return;
    const unsigned* bw = bits + (size_t)bt * 32;
    int* np = nbr + (size_t)bt * NBCAP;
    int c = 0;
    #pragma unroll 4
    for (int w = 0; w < 32; w++) {
        unsigned m = bw[w];
        while (m) {
            int bit = __ffs(m) - 1;
            m &= m - 1;
            if (c < NBCAP) np[c] = w * 32 + bit;
            c++;
        }
    }
    cnt[bt] = c < NBCAP ? c : NBCAP;
}

// ---------------- fused fp32 -> fp16 convert of all weights + emb ----------------
#define CV_N1 (MTOT*DD)            // emb
#define CV_N2 (LGN*HH*DD*DD)       // gatW
#define CV_N3 (LTN*DD*DD)          // Wo
#define CV_N4 (LTN*DD*DFFX)        // W1
#define CV_N5 (LTN*DFFX*DD)        // W2
#define CV_TOT (CV_N1+CV_N2+CV_N3+CV_N4+CV_N5)

__global__ void cvt_all_k(const float* __restrict__ emb, const float* __restrict__ gatW,
                          const float* __restrict__ Wo, const float* __restrict__ W1,
                          const float* __restrict__ W2)
{
    int i = (blockIdx.x * 256 + threadIdx.x) * 4;
    if (i >= CV_TOT) return;
    const float* src; __half* dst; int off;
    if (i < CV_N1)                         { src = emb;  dst = g_EMBH;  off = i; }
    else if (i < CV_N1 + CV_N2)            { src = gatW; dst = g_GATWH; off = i - CV_N1; }
    else if (i < CV_N1 + CV_N2 + CV_N3)    { src = Wo;   dst = g_WOH;   off = i - CV_N1 - CV_N2; }
    else if (i < CV_N1 + CV_N2 + CV_N3 + CV_N4)
                                           { src = W1;   dst = g_W1H;   off = i - CV_N1 - CV_N2 - CV_N3; }
    else                                   { src = W2;   dst = g_W2H;   off = i - CV_N1 - CV_N2 - CV_N3 - CV_N4; }
    float4 v = *(const float4*)(src + off);
    *(__half2*)(dst + off)     = __floats2half2_rn(v.x, v.y);
    *(__half2*)(dst + off + 2) = __floats2half2_rn(v.z, v.w);
}

// ---------------- QKV pack ----------------
__global__ void pack_qkv_k(const float* __restrict__ Wq, const float* __restrict__ Wk,
                           const float* __restrict__ Wv, const float* __restrict__ bq,
                           const float* __restrict__ bk, const float* __restrict__ bv,
                           __half* __restrict__ W, float* __restrict__ Bb)
{
    int idx = blockIdx.x * 256 + threadIdx.x;
    if (idx >= LTN * DD * 3 * DD) return;
    int n = idx % (3 * DD);
    int k = (idx / (3 * DD)) % DD;
    int l = idx / (3 * DD * DD);
    float v;
    if (n < DD)            v = Wq[((size_t)l * DD + k) * DD + n];
    else if (n < 2 * DD)   v = Wk[((size_t)l * DD + k) * DD + n - DD];
    else                   v = Wv[((size_t)l * DD + k) * DD + n - 2 * DD];
    W[idx] = __float2half_rn(v);
    if (k == 0) {
        float bvv;
        if (n < DD)          bvv = bq[l * DD + n];
        else if (n < 2 * DD) bvv = bk[l * DD + n - DD];
        else                 bvv = bv[l * DD + n - 2 * DD];
        Bb[l * 3 * DD + n] = bvv;
    }
}

// ---------------- fp16 tensor-core GEMM: 2-stage cp.async + ldmatrix (R8) ----------------
template<bool BT, int ACT, int HALF_OUT, int ASAD>
__global__ void __launch_bounds__(256) hgemm_k(
    int M, int Ncol, int K,
    const __half* __restrict__ A, int lda,
    const __half* __restrict__ B, int ldb,
    void* __restrict__ Cv, int ldc,
    const float* __restrict__ bias,
    const float* __restrict__ attS, const float* __restrict__ attD,
    float* __restrict__ ASP, float* __restrict__ ADP)
{
    __shared__ __align__(16) __half sA[2][128 * 24];
    __shared__ __align__(16) __half sB[2][3072];
    const int tid  = threadIdx.x;
    const int lane = tid & 31, wid = tid >> 5;
    const int wm = wid & 3, wn = wid >> 2;
    const int m0 = blockIdx.y * 128, n0 = blockIdx.x * 128;
    const int r = lane >> 2, cq = lane & 3;

    float acc[2][8][4];
    #pragma unroll
    for (int mt = 0; mt < 2; mt++)
        #pragma unroll
        for (int nt = 0; nt < 8; nt++)
            #pragma unroll
            for (int u = 0; u < 4; u++) acc[mt][nt][u] = 0.f;

    const int T = K / 16;

    auto loadT = [&](int st, int k0) {
        {
            int m = tid >> 1, c = tid & 1;
            cp16(saddr(&sA[st][m * 24 + c * 8]), A + (size_t)(m0 + m) * lda + k0 + c * 8);
        }
        if (BT) {
            int n = tid >> 1, c = tid & 1;
            cp16(saddr(&sB[st][n * 24 + c * 8]), B + (size_t)(n0 + n) * ldb + k0 + c * 8);
        } else {
            int kk = tid >> 4, c = tid & 15;
            cp16(saddr(&sB[st][kk * 136 + c * 8]), B + (size_t)(k0 + kk) * ldb + n0 + c * 8);
        }
        cp_commit();
    };

    loadT(0, 0);
    for (int t = 0; t < T; t++) {
        if (t + 1 < T) { loadT((t + 1) & 1, (t + 1) * 16); cp_wait<1>(); }
        else           { cp_wait<0>(); }
        __syncthreads();
        const int st = t & 1;

        unsigned af[2][4], bf[8][2];
        #pragma unroll
        for (int mt = 0; mt < 2; mt++) {
            int mrow = wm * 32 + mt * 16;
            unsigned addr = saddr(&sA[st][(mrow + (lane & 15)) * 24 + (lane >> 4) * 8]);
            ldsm4(af[mt][0], af[mt][1], af[mt][2], af[mt][3], addr);
        }
        #pragma unroll
        for (int p = 0; p < 4; p++) {
            int nb = wn * 64 + p * 16;
            if (BT) {
                int row = nb + (lane & 7) + ((lane >> 4) << 3);
                int col = ((lane >> 3) & 1) * 8;
                unsigned addr = saddr(&sB[st][row * 24 + col]);
                ldsm4(bf[2 * p][0], bf[2 * p][1], bf[2 * p + 1][0], bf[2 * p + 1][1], addr);
            } else {
                int krow = (lane & 7) + (((lane >> 3) & 1) << 3);
                int coln = nb + (lane >> 4) * 8;
                unsigned addr = saddr(&sB[st][krow * 136 + coln]);
                ldsm4t(bf[2 * p][0], bf[2 * p][1], bf[2 * p + 1][0], bf[2 * p + 1][1], addr);
            }
        }
        #pragma unroll
        for (int mt = 0; mt < 2; mt++)
            #pragma unroll
            for (int nt = 0; nt < 8; nt++)
                mma_f16(acc[mt][nt], af[mt], bf[nt]);
        __syncthreads();
    }

    if (ASAD) {
        float sS[2][2] = {{0,0},{0,0}}, sD[2][2] = {{0,0},{0,0}};
        #pragma unroll
        for (int mt = 0; mt < 2; mt++)
            #pragma unroll
            for (int nt = 0; nt < 8; nt++)
                #pragma unroll
                for (int u = 0; u < 4; u++) {
                    int g = n0 + wn * 64 + nt * 8 + cq * 2 + (u & 1);
                    float v = acc[mt][nt][u];
                    sS[mt][u >> 1] += v * attS[g];
                    sD[mt][u >> 1] += v * attD[g];
                }
        #pragma unroll
        for (int o = 1; o <= 2; o <<= 1)
            #pragma unroll
            for (int mt = 0; mt < 2; mt++)
                #pragma unroll
                for (int q = 0; q < 2; q++) {
                    sS[mt][q] += __shfl_xor_sync(0xffffffffu, sS[mt][q], o);
                    sD[mt][q] += __shfl_xor_sync(0xffffffffu, sD[mt][q], o);
                }
        if (cq == 0) {
            int j = (n0 >> 6) + wn;
            #pragma unroll
            for (int mt = 0; mt < 2; mt++)
                #pragma unroll
                for (int q = 0; q < 2; q++) {
                    int row = m0 + wm * 32 + mt * 16 + r + q * 8;
                    ASP[(size_t)j * M + row] = sS[mt][q];
                    ADP[(size_t)j * M + row] = sD[mt][q];
                }
        }
    }

    #pragma unroll
    for (int mt = 0; mt < 2; mt++) {
        int mrow = m0 + wm * 32 + mt * 16 + r;
        #pragma unroll
        for (int nt = 0; nt < 8; nt++) {
            int ncol = n0 + wn * 64 + nt * 8 + cq * 2;
            float* ac = acc[mt][nt];
            float2 v0 = make_float2(ac[0], ac[1]);
            float2 v1 = make_float2(ac[2], ac[3]);
            if (bias) {
                float b0 = bias[ncol], b1 = bias[ncol + 1];
                v0.x += b0; v0.y += b1; v1.x += b0; v1.y += b1;
            }
            if (ACT == 1) {
                v0.x = fmaxf(v0.x, 0.f); v0.y = fmaxf(v0.y, 0.f);
                v1.x = fmaxf(v1.x, 0.f); v1.y = fmaxf(v1.y, 0.f);
            }
            if (HALF_OUT) {
                __half* Ch = (__half*)Cv;
                *(__half2*)(Ch + (size_t)mrow * ldc + ncol) = __floats2half2_rn(v0.x, v0.y);
                *(__half2*)(Ch + (size_t)(mrow + 8) * ldc + ncol) = __floats2half2_rn(v1.x, v1.y);
            } else {
                float* Cf = (float*)Cv;
                *(float2*)(Cf + (size_t)mrow * ldc + ncol) = v0;
                *(float2*)(Cf + (size_t)(mrow + 8) * ldc + ncol) = v1;
            }
        }
    }
}

// ---------------- asad reduce ----------------
__global__ void asad_reduce_k(const float* __restrict__ ASP, const float* __restrict__ ADP,
                              float* __restrict__ as_, float* __restrict__ ad_)
{
    int idx = blockIdx.x * 256 + threadIdx.x;
    int row = idx >> 3, h = idx & 7;
    float s = 0.f, d = 0.f;
    #pragma unroll
    for (int j = 4 * h; j < 4 * h + 4; j++) {
        s += ASP[(size_t)j * MTOT + row];
        d += ADP[(size_t)j * MTOT + row];
    }
    as_[row * 8 + h] = s;
    ad_[row * 8 + h] = d;
}

// ---------------- sparse GAT aggregation (fp16; warp = head, lane = 8 cols) ----------------
__global__ void __launch_bounds__(256) gat_agg_k(
    const __half* __restrict__ hb, const float* __restrict__ as_,
    const float* __restrict__ ad_, const int* __restrict__ nbr,
    const int* __restrict__ cnt, const float* __restrict__ bias,
    float* __restrict__ y, __half* __restrict__ yh)
{
    __shared__ int   s_nbr[NBCAP];
    __shared__ float s_alpha[HH][NBCAP];
    __shared__ float s_inv[HH];
    __shared__ float s_red[HH][DD];
    int bt  = blockIdx.x;
    int b   = bt >> 10;
    int tid = threadIdx.x;
    int nc  = cnt[bt];
    for (int j = tid; j < nc; j += 256) s_nbr[j] = nbr[(size_t)bt * NBCAP + j];
    __syncthreads();

    for (int j = tid; j < nc; j += 256) {
        int s = s_nbr[j];
        const float* ap = as_ + (size_t)(b * NNODE + s) * HH;
        #pragma unroll
        for (int h = 0; h < HH; h++) {
            float e = ad_[bt * HH + h] + ap[h];
            e = e >= 0.f ? e : 0.2f * e;
            s_alpha[h][j] = __expf(e);
        }
    }
    __syncthreads();

    int h    = tid >> 5;
    int lane = tid & 31;
    {
        float sum = 0.f;
        for (int j = lane; j < nc; j += 32) sum += s_alpha[h][j];
        #pragma unroll
        for (int o = 16; o; o >>= 1) sum += __shfl_xor_sync(0xffffffffu, sum, o);
        if (lane == 0) s_inv[h] = 1.f / (8.f * sum);
    }
    __syncthreads();
    for (int j = tid; j < nc; j += 256) {
        #pragma unroll
        for (int hh = 0; hh < HH; hh++) s_alpha[hh][j] *= s_inv[hh];
    }
    __syncthreads();

    const __half* hbase = hb + (size_t)b * NNODE * (HH * DD) + h * DD + lane * 8;
    float a[8];
    #pragma unroll
    for (int i = 0; i < 8; i++) a[i] = 0.f;
    #pragma unroll 2
    for (int j = 0; j < nc; j++) {
        float w = s_alpha[h][j];
        const float4* p = (const float4*)(hbase + (size_t)s_nbr[j] * (HH * DD));
        float4 raw = *p;
        const __half2* h2 = (const __half2*)&raw;
        #pragma unroll
        for (int i = 0; i < 4; i++) {
            float2 u = __half22float2(h2[i]);
            a[2 * i]     = fmaf(w, u.x, a[2 * i]);
            a[2 * i + 1] = fmaf(w, u.y, a[2 * i + 1]);
        }
    }
    #pragma unroll
    for (int i = 0; i < 8; i += 4)
        *(float4*)&s_red[h][lane * 8 + i] = make_float4(a[i], a[i+1], a[i+2], a[i+3]);
    __syncthreads();

    {
        int c = tid;
        float v = bias[c];
        #pragma unroll
        for (int hh = 0; hh < HH; hh++) v += s_red[hh][c];
        y[(size_t)bt * DD + c] = v;
        yh[(size_t)bt * DD + c] = __float2half_rn(v);
    }
}

// ---------------- sparse masked attention: two-pass, no per-edge shuffles ----------------
// Pass 1 (lane = edge): w_j = exp(q.k_j) via in-register half2 dot; Σw once per warp.
// Pass 2 (lane = channel): o_ch = Σ_j w_j * V[j][ch] (fp32), then * 1/Σw.
__global__ void __launch_bounds__(256) attn_sparse_k(
    const __half* __restrict__ QKV, const int* __restrict__ nbr,
    const int* __restrict__ cnt, __half* __restrict__ Om)
{
    __shared__ int   s_nbr[NBCAP];
    __shared__ float s_w[HH][NBCAP];
    __shared__ float s_winv[HH];
    int bt  = blockIdx.x;
    int b   = bt >> 10;
    int tid = threadIdx.x;
    int nc  = cnt[bt];
    for (int j = tid; j < nc; j += 256) s_nbr[j] = nbr[(size_t)bt * NBCAP + j];
    __syncthreads();
    int h = tid >> 5, lane = tid & 31;
    const int LD3 = 3 * DD;

    // load q (32 halves, broadcast) and pre-scale
    unsigned qh[16];
    {
        const uint4* qp = (const uint4*)(QKV + (size_t)bt * LD3 + h * DHH);
        const __half2 sc2 = __floats2half2_rn(0.17677669529663687f, 0.17677669529663687f);
        #pragma unroll
        for (int i = 0; i < 4; i++) {
            uint4 v = qp[i];
            unsigned* u = (unsigned*)&v;
            #pragma unroll
            for (int k = 0; k < 4; k++) {
                __half2 hv = __hmul2(*(__half2*)&u[k], sc2);
                qh[i * 4 + k] = *(unsigned*)&hv;
            }
        }
    }

    // pass 1: lane = edge
    float aw = 0.f;
    for (int j = lane; j < nc; j += 32) {
        int s = s_nbr[j];
        const uint4* kp = (const uint4*)(QKV + (size_t)(b * NNODE + s) * LD3 + DD + h * DHH);
        __half2 acc2 = __floats2half2_rn(0.f, 0.f);
        #pragma unroll
        for (int i = 0; i < 4; i++) {
            uint4 v = kp[i];
            unsigned* u = (unsigned*)&v;
            #pragma unroll
            for (int k = 0; k < 4; k++)
                acc2 = __hfma2(*(__half2*)&u[k], *(__half2*)&qh[i * 4 + k], acc2);
        }
        float2 f = __half22float2(acc2);
        float w = __expf(f.x + f.y);
        s_w[h][j] = w;
        aw += w;
    }
    #pragma unroll
    for (int o = 16; o; o >>= 1) aw += __shfl_xor_sync(0xffffffffu, aw, o);
    if (lane == 0) s_winv[h] = 1.f / aw;
    __syncwarp();

    // pass 2: lane = channel
    const __half* vbase = QKV + (size_t)b * NNODE * LD3 + 2 * DD + h * DHH + lane;
    float accv = 0.f;
    int j = 0;
    for (; j + 4 <= nc; j += 4) {
        #pragma unroll
        for (int u = 0; u < 4; u++) {
            int s = s_nbr[j + u];
            accv = fmaf(s_w[h][j + u], __half2float(vbase[(size_t)s * LD3]), accv);
        }
    }
    for (; j < nc; j++) {
        int s = s_nbr[j];
        accv = fmaf(s_w[h][j], __half2float(vbase[(size_t)s * LD3]), accv);
    }
    Om[(size_t)bt * DD + h * DHH + lane] = __float2half_rn(accv * s_winv[h]);
}

// ---------------- layernorm: warp per row ----------------
template<int MODE, int WRITEH>
__global__ void __launch_bounds__(256) ln_warp_k(
    const float* __restrict__ a, const float* __restrict__ bsrc,
    const float* __restrict__ gam, const float* __restrict__ bet,
    float* __restrict__ out, __half* __restrict__ outh)
{
    int row  = blockIdx.x * 8 + (threadIdx.x >> 5);
    int lane = threadIdx.x & 31;
    size_t base = (size_t)row * DD;
    float v[8];
    float sum = 0.f;
    #pragma unroll
    for (int p = 0; p < 2; p++) {
        int c = lane * 4 + p * 128;
        float4 av = *(const float4*)(a + base + c);
        float4 bv = *(const float4*)(bsrc + base + c);
        if (MODE == 1) {
            bv.x = fmaxf(bv.x, 0.f); bv.y = fmaxf(bv.y, 0.f);
            bv.z = fmaxf(bv.z, 0.f); bv.w = fmaxf(bv.w, 0.f);
        }
        v[p*4+0] = av.x + bv.x; v[p*4+1] = av.y + bv.y;
        v[p*4+2] = av.z + bv.z; v[p*4+3] = av.w + bv.w;
        sum += v[p*4+0] + v[p*4+1] + v[p*4+2] + v[p*4+3];
    }
    #pragma unroll
    for (int o = 16; o; o >>= 1) sum += __shfl_xor_sync(0xffffffffu, sum, o);
    float mean = sum * (1.f / DD);
    float var = 0.f;
    #pragma unroll
    for (int i = 0; i < 8; i++) { float d = v[i] - mean; var += d * d; }
    #pragma unroll
    for (int o = 16; o; o >>= 1) var += __shfl_xor_sync(0xffffffffu, var, o);
    float rstd = rsqrtf(var * (1.f / DD) + 1e-5f);
    #pragma unroll
    for (int p = 0; p < 2; p++) {
        int c = lane * 4 + p * 128;
        float4 g = *(const float4*)(gam + c);
        float4 bb = *(const float4*)(bet + c);
        float4 o4;
        o4.x = (v[p*4+0] - mean) * rstd * g.x + bb.x;
        o4.y = (v[p*4+1] - mean) * rstd * g.y + bb.y;
        o4.z = (v[p*4+2] - mean) * rstd * g.z + bb.z;
        o4.w = (v[p*4+3] - mean) * rstd * g.w + bb.w;
        *(float4*)(out + base + c) = o4;
        if (WRITEH) {
            __half2 h0 = __floats2half2_rn(o4.x, o4.y);
            __half2 h1 = __floats2half2_rn(o4.z, o4.w);
            *(uint2*)(outh + base + c) = make_uint2(*(unsigned*)&h0, *(unsigned*)&h1);
        }
    }
}

extern "C" void kernel_launch(void* const* d_in, const int* in_sizes, int n_in,
                              void* d_out, int out_size)
{
    const float* emb  = (const float*)d_in[0];
    const int*   mask = (const int*)  d_in[2];
    const float* gatW = (const float*)d_in[4];
    const float* attS = (const float*)d_in[5];
    const float* attD = (const float*)d_in[6];
    const float* gatB = (const float*)d_in[7];
    const float* glnS = (const float*)d_in[8];
    const float* glnB = (const float*)d_in[9];
    const float* Wq = (const float*)d_in[10], *bq = (const float*)d_in[11];
    const float* Wk = (const float*)d_in[12], *bk = (const float*)d_in[13];
    const float* Wv = (const float*)d_in[14], *bv = (const float*)d_in[15];
    const float* Wo = (const float*)d_in[16], *bo = (const float*)d_in[17];
    const float* W1 = (const float*)d_in[18], *b1 = (const float*)d_in[19];
    const float* W2 = (const float*)d_in[20], *b2 = (const float*)d_in[21];
    const float* l1s = (const float*)d_in[22], *l1b = (const float*)d_in[23];
    const float* l2s = (const float*)d_in[24], *l2b = (const float*)d_in[25];
    float* out = (float*)d_out;

    float *XC,*AS,*AD,*ASP,*ADP,*BQKV,*Y;
    __half *XCH,*EMBH,*HBH,*QKVH,*WQKVH,*GATWH,*WOH,*W1H,*W2H,*AOH,*YH,*FFH;
    unsigned* BITS; int *NBR,*CNT;
    cudaGetSymbolAddress((void**)&XC, g_XC);
    cudaGetSymbolAddress((void**)&XCH, g_XCH);
    cudaGetSymbolAddress((void**)&EMBH, g_EMBH);
    cudaGetSymbolAddress((void**)&HBH, g_HBH);
    cudaGetSymbolAddress((void**)&AS, g_AS);
    cudaGetSymbolAddress((void**)&AD, g_AD);
    cudaGetSymbolAddress((void**)&ASP, g_ASP);
    cudaGetSymbolAddress((void**)&ADP, g_ADP);
    cudaGetSymbolAddress((void**)&QKVH, g_QKVH);
    cudaGetSymbolAddress((void**)&WQKVH, g_WQKVH);
    cudaGetSymbolAddress((void**)&BQKV, g_BQKV);
    cudaGetSymbolAddress((void**)&GATWH, g_GATWH);
    cudaGetSymbolAddress((void**)&WOH, g_WOH);
    cudaGetSymbolAddress((void**)&W1H, g_W1H);
    cudaGetSymbolAddress((void**)&W2H, g_W2H);
    cudaGetSymbolAddress((void**)&AOH, g_AOH);
    cudaGetSymbolAddress((void**)&Y,  g_Y);
    cudaGetSymbolAddress((void**)&YH, g_YH);
    cudaGetSymbolAddress((void**)&FFH, g_FFH);
    cudaGetSymbolAddress((void**)&BITS, g_BITS);
    cudaGetSymbolAddress((void**)&NBR, g_NBR);
    cudaGetSymbolAddress((void**)&CNT, g_CNT);

    const int M = MTOT;

    pack_adj_k<<<(BB*32*NNODE)/256, 256>>>(mask, BITS);
    build_nbr_k<<<(MTOT)/256, 256>>>(BITS, NBR, CNT);
    pack_qkv_k<<<(LTN*DD*3*DD + 255)/256, 256>>>(Wq, Wk, Wv, bq, bk, bv, WQKVH, BQKV);
    cvt_all_k<<<(CV_TOT/4 + 255)/256, 256>>>(emb, gatW, Wo, W1, W2);

    // ---- GAT stack ----
    const __half* x = EMBH;
    for (int l = 0; l < LGN; l++) {
        hgemm_k<true,0,1,1><<<dim3((HH*DD)/128, M/128), 256>>>(
            M, HH*DD, DD, x, DD, GATWH + (size_t)l*HH*DD*DD, DD,
            HBH, HH*DD, nullptr, attS + l*HH*DD, attD + l*HH*DD, ASP, ADP);
        asad_reduce_k<<<(MTOT*8)/256, 256>>>(ASP, ADP, AS, AD);
        gat_agg_k<<<M, 256>>>(HBH, AS, AD, NBR, CNT, gatB + l*DD, Y, YH);
        x = YH;
    }
    ln_warp_k<1,1><<<M/8, 256>>>(emb, Y, glnS, glnB, XC, XCH);

    // ---- transformer layers ----
    for (int l = 0; l < LTN; l++) {
        hgemm_k<false,0,1,0><<<dim3((3*DD)/128, M/128), 256>>>(
            M, 3*DD, DD, XCH, DD, WQKVH + (size_t)l*DD*3*DD, 3*DD, QKVH, 3*DD,
            BQKV + l*3*DD, nullptr, nullptr, nullptr, nullptr);
        attn_sparse_k<<<M, 256>>>(QKVH, NBR, CNT, AOH);
        hgemm_k<false,0,0,0><<<dim3(DD/128, M/128), 256>>>(
            M, DD, DD, AOH, DD, WOH + (size_t)l*DD*DD, DD, Y, DD,
            bo + l*DD, nullptr, nullptr, nullptr, nullptr);
        ln_warp_k<0,1><<<M/8, 256>>>(XC, Y, l1s + l*DD, l1b + l*DD, XC, XCH);
        hgemm_k<false,1,1,0><<<dim3(DFFX/128, M/128), 256>>>(
            M, DFFX, DD, XCH, DD, W1H + (size_t)l*DD*DFFX, DFFX, FFH, DFFX,
            b1 + l*DFFX, nullptr, nullptr, nullptr, nullptr);
        hgemm_k<false,0,0,0><<<dim3(DD/128, M/128), 256>>>(
            M, DD, DFFX, FFH, DFFX, W2H + (size_t)l*DFFX*DD, DD, Y, DD,
            b2 + l*DD, nullptr, nullptr, nullptr, nullptr);
        if (l == LTN - 1)
            ln_warp_k<0,0><<<M/8, 256>>>(XC, Y, l2s + l*DD, l2b + l*DD, out, nullptr);
        else
            ln_warp_k<0,1><<<M/8, 256>>>(XC, Y, l2s + l*DD, l2b + l*DD, XC, XCH);
    }
}

// round 12
// speedup vs baseline: 1.3362x; 1.0462x over previous
#include <cuda_runtime.h>
#include <cuda_fp16.h>
#include <math.h>

// ---------------- dims ----------------
#define BB    8
#define NNODE 1024
#define DD    256
#define HH    8
#define DHH   32
#define DFFX  1024
#define LGN   2
#define LTN   2
#define NBCAP 256
#define MTOT  (BB*NNODE)
#define SPLK  4

// ---------------- scratch (device globals; no runtime allocation) ----------------
__device__ float                 g_XC[MTOT*DD];
__device__ __align__(16) __half  g_XCH[MTOT*DD];
__device__ __align__(16) __half  g_EMBH[MTOT*DD];
__device__ __align__(16) __half  g_HBH[MTOT*HH*DD];
__device__ float                 g_AS[MTOT*HH];
__device__ float                 g_AD[MTOT*HH];
__device__ float                 g_ASP[32*MTOT];
__device__ float                 g_ADP[32*MTOT];
__device__ __align__(16) __half  g_QKVH[MTOT*3*DD];
__device__ __align__(16) __half  g_WQKVH[LTN*DD*3*DD];
__device__ float                 g_BQKV[LTN*3*DD];
__device__ __align__(16) __half  g_GATWH[LGN*HH*DD*DD];
__device__ __align__(16) __half  g_WOH[LTN*DD*DD];
__device__ __align__(16) __half  g_W1H[LTN*DD*DFFX];
__device__ __align__(16) __half  g_W2H[LTN*DFFX*DD];
__device__ __align__(16) __half  g_AOH[MTOT*DD];
__device__ float                 g_Y [MTOT*DD];
__device__ __align__(16) __half  g_YH[MTOT*DD];
__device__ __align__(16) __half  g_FFH[MTOT*DFFX];
__device__ float                 g_PART[SPLK*MTOT*DD];   // split-K partials
__device__ unsigned              g_BITS[MTOT*(NNODE/32)];
__device__ int                   g_NBR[MTOT*NBCAP];
__device__ int                   g_CNT[MTOT];

// ---------------- helpers ----------------
__device__ __forceinline__ void mma_f16(float* c, const unsigned* a, const unsigned* b) {
    asm volatile(
        "mma.sync.aligned.m16n8k16.row.col.f32.f16.f16.f32 "
        "{%0,%1,%2,%3}, {%4,%5,%6,%7}, {%8,%9}, {%0,%1,%2,%3};\n"
        : "+f"(c[0]), "+f"(c[1]), "+f"(c[2]), "+f"(c[3])
        : "r"(a[0]), "r"(a[1]), "r"(a[2]), "r"(a[3]), "r"(b[0]), "r"(b[1]));
}

__device__ __forceinline__ unsigned saddr(const void* p) {
    return (unsigned)__cvta_generic_to_shared(p);
}
__device__ __forceinline__ void cp16(unsigned dst, const void* src) {
    asm volatile("cp.async.cg.shared.global [%0], [%1], 16;\n" :: "r"(dst), "l"(src));
}
__device__ __forceinline__ void cp_commit() {
    asm volatile("cp.async.commit_group;\n" ::: "memory");
}
template<int N>
__device__ __forceinline__ void cp_wait() {
    asm volatile("cp.async.wait_group %0;\n" :: "n"(N) : "memory");
}
__device__ __forceinline__ void ldsm4(unsigned& r0, unsigned& r1, unsigned& r2, unsigned& r3,
                                      unsigned addr) {
    asm volatile("ldmatrix.sync.aligned.m8n8.x4.shared.b16 {%0,%1,%2,%3}, [%4];"
                 : "=r"(r0), "=r"(r1), "=r"(r2), "=r"(r3) : "r"(addr));
}
__device__ __forceinline__ void ldsm4t(unsigned& r0, unsigned& r1, unsigned& r2, unsigned& r3,
                                       unsigned addr) {
    asm volatile("ldmatrix.sync.aligned.m8n8.x4.trans.shared.b16 {%0,%1,%2,%3}, [%4];"
                 : "=r"(r0), "=r"(r1), "=r"(r2), "=r"(r3) : "r"(addr));
}

// ---------------- adjacency pack ----------------
__global__ void pack_adj_k(const int* __restrict__ mask, unsigned* __restrict__ bits) {
    int idx = blockIdx.x * blockDim.x + threadIdx.x;
    int t  = idx & (NNODE - 1);
    int sw = (idx >> 10) & 31;
    int b  = idx >> 15;
    const int* mp = mask + ((size_t)b * NNODE + (size_t)sw * 32) * NNODE + t;
    unsigned w = 0;
    #pragma unroll
    for (int i = 0; i < 32; i++)
        if (mp[(size_t)i * NNODE] > 0) w |= (1u << i);
    int s0 = sw * 32;
    if (t >= s0 && t < s0 + 32) w |= (1u << (t - s0));
    bits[(b * NNODE + t) * 32 + sw] = w;
}

// ---------------- neighbor list build ----------------
__global__ void build_nbr_k(const unsigned* __restrict__ bits,
                            int* __restrict__ nbr, int* __restrict__ cnt) {
    int bt = blockIdx.x * blockDim.x + threadIdx.x;
    if (bt >= MTOT) return;
    const unsigned* bw = bits + (size_t)bt * 32;
    int* np = nbr + (size_t)bt * NBCAP;
    int c = 0;
    #pragma unroll 4
    for (int w = 0; w < 32; w++) {
        unsigned m = bw[w];
        while (m) {
            int bit = __ffs(m) - 1;
            m &= m - 1;
            if (c < NBCAP) np[c] = w * 32 + bit;
            c++;
        }
    }
    cnt[bt] = c < NBCAP ? c : NBCAP;
}

// ---------------- fused fp32 -> fp16 convert of all weights + emb ----------------
#define CV_N1 (MTOT*DD)
#define CV_N2 (LGN*HH*DD*DD)
#define CV_N3 (LTN*DD*DD)
#define CV_N4 (LTN*DD*DFFX)
#define CV_N5 (LTN*DFFX*DD)
#define CV_TOT (CV_N1+CV_N2+CV_N3+CV_N4+CV_N5)

__global__ void cvt_all_k(const float* __restrict__ emb, const float* __restrict__ gatW,
                          const float* __restrict__ Wo, const float* __restrict__ W1,
                          const float* __restrict__ W2)
{
    int i = (blockIdx.x * 256 + threadIdx.x) * 4;
    if (i >= CV_TOT) return;
    const float* src; __half* dst; int off;
    if (i < CV_N1)                         { src = emb;  dst = g_EMBH;  off = i; }
    else if (i < CV_N1 + CV_N2)            { src = gatW; dst = g_GATWH; off = i - CV_N1; }
    else if (i < CV_N1 + CV_N2 + CV_N3)    { src = Wo;   dst = g_WOH;   off = i - CV_N1 - CV_N2; }
    else if (i < CV_N1 + CV_N2 + CV_N3 + CV_N4)
                                           { src = W1;   dst = g_W1H;   off = i - CV_N1 - CV_N2 - CV_N3; }
    else                                   { src = W2;   dst = g_W2H;   off = i - CV_N1 - CV_N2 - CV_N3 - CV_N4; }
    float4 v = *(const float4*)(src + off);
    *(__half2*)(dst + off)     = __floats2half2_rn(v.x, v.y);
    *(__half2*)(dst + off + 2) = __floats2half2_rn(v.z, v.w);
}

// ---------------- QKV pack ----------------
__global__ void pack_qkv_k(const float* __restrict__ Wq, const float* __restrict__ Wk,
                           const float* __restrict__ Wv, const float* __restrict__ bq,
                           const float* __restrict__ bk, const float* __restrict__ bv,
                           __half* __restrict__ W, float* __restrict__ Bb)
{
    int idx = blockIdx.x * 256 + threadIdx.x;
    if (idx >= LTN * DD * 3 * DD) return;
    int n = idx % (3 * DD);
    int k = (idx / (3 * DD)) % DD;
    int l = idx / (3 * DD * DD);
    float v;
    if (n < DD)            v = Wq[((size_t)l * DD + k) * DD + n];
    else if (n < 2 * DD)   v = Wk[((size_t)l * DD + k) * DD + n - DD];
    else                   v = Wv[((size_t)l * DD + k) * DD + n - 2 * DD];
    W[idx] = __float2half_rn(v);
    if (k == 0) {
        float bvv;
        if (n < DD)          bvv = bq[l * DD + n];
        else if (n < 2 * DD) bvv = bk[l * DD + n - DD];
        else                 bvv = bv[l * DD + n - 2 * DD];
        Bb[l * 3 * DD + n] = bvv;
    }
}

// ---------------- fp16 tensor-core GEMM: 2-stage cp.async + ldmatrix ----------------
// SPLITZ>1: grid.z splits K; C is fp32 partial buffer [z][M*Ncol], bias must be null.
template<bool BT, int ACT, int HALF_OUT, int ASAD, int SPLITZ>
__global__ void __launch_bounds__(256) hgemm_k(
    int M, int Ncol, int K,
    const __half* __restrict__ A, int lda,
    const __half* __restrict__ B, int ldb,
    void* __restrict__ Cv, int ldc,
    const float* __restrict__ bias,
    const float* __restrict__ attS, const float* __restrict__ attD,
    float* __restrict__ ASP, float* __restrict__ ADP)
{
    if (SPLITZ > 1) {
        int Kc = K / SPLITZ;
        A += (size_t)blockIdx.z * Kc;
        B += (size_t)blockIdx.z * Kc * ldb;   // !BT layouts only
        Cv = (void*)((float*)Cv + (size_t)blockIdx.z * M * Ncol);
        K = Kc;
    }
    __shared__ __align__(16) __half sA[2][128 * 24];
    __shared__ __align__(16) __half sB[2][3072];
    const int tid  = threadIdx.x;
    const int lane = tid & 31, wid = tid >> 5;
    const int wm = wid & 3, wn = wid >> 2;
    const int m0 = blockIdx.y * 128, n0 = blockIdx.x * 128;
    const int r = lane >> 2, cq = lane & 3;

    float acc[2][8][4];
    #pragma unroll
    for (int mt = 0; mt < 2; mt++)
        #pragma unroll
        for (int nt = 0; nt < 8; nt++)
            #pragma unroll
            for (int u = 0; u < 4; u++) acc[mt][nt][u] = 0.f;

    const int T = K / 16;

    auto loadT = [&](int st, int k0) {
        {
            int m = tid >> 1, c = tid & 1;
            cp16(saddr(&sA[st][m * 24 + c * 8]), A + (size_t)(m0 + m) * lda + k0 + c * 8);
        }
        if (BT) {
            int n = tid >> 1, c = tid & 1;
            cp16(saddr(&sB[st][n * 24 + c * 8]), B + (size_t)(n0 + n) * ldb + k0 + c * 8);
        } else {
            int kk = tid >> 4, c = tid & 15;
            cp16(saddr(&sB[st][kk * 136 + c * 8]), B + (size_t)(k0 + kk) * ldb + n0 + c * 8);
        }
        cp_commit();
    };

    loadT(0, 0);
    for (int t = 0; t < T; t++) {
        if (t + 1 < T) { loadT((t + 1) & 1, (t + 1) * 16); cp_wait<1>(); }
        else           { cp_wait<0>(); }
        __syncthreads();
        const int st = t & 1;

        unsigned af[2][4], bf[8][2];
        #pragma unroll
        for (int mt = 0; mt < 2; mt++) {
            int mrow = wm * 32 + mt * 16;
            unsigned addr = saddr(&sA[st][(mrow + (lane & 15)) * 24 + (lane >> 4) * 8]);
            ldsm4(af[mt][0], af[mt][1], af[mt][2], af[mt][3], addr);
        }
        #pragma unroll
        for (int p = 0; p < 4; p++) {
            int nb = wn * 64 + p * 16;
            if (BT) {
                int row = nb + (lane & 7) + ((lane >> 4) << 3);
                int col = ((lane >> 3) & 1) * 8;
                unsigned addr = saddr(&sB[st][row * 24 + col]);
                ldsm4(bf[2 * p][0], bf[2 * p][1], bf[2 * p + 1][0], bf[2 * p + 1][1], addr);
            } else {
                int krow = (lane & 7) + (((lane >> 3) & 1) << 3);
                int coln = nb + (lane >> 4) * 8;
                unsigned addr = saddr(&sB[st][krow * 136 + coln]);
                ldsm4t(bf[2 * p][0], bf[2 * p][1], bf[2 * p + 1][0], bf[2 * p + 1][1], addr);
            }
        }
        #pragma unroll
        for (int mt = 0; mt < 2; mt++)
            #pragma unroll
            for (int nt = 0; nt < 8; nt++)
                mma_f16(acc[mt][nt], af[mt], bf[nt]);
        __syncthreads();
    }

    if (ASAD) {
        float sS[2][2] = {{0,0},{0,0}}, sD[2][2] = {{0,0},{0,0}};
        #pragma unroll
        for (int mt = 0; mt < 2; mt++)
            #pragma unroll
            for (int nt = 0; nt < 8; nt++)
                #pragma unroll
                for (int u = 0; u < 4; u++) {
                    int g = n0 + wn * 64 + nt * 8 + cq * 2 + (u & 1);
                    float v = acc[mt][nt][u];
                    sS[mt][u >> 1] += v * attS[g];
                    sD[mt][u >> 1] += v * attD[g];
                }
        #pragma unroll
        for (int o = 1; o <= 2; o <<= 1)
            #pragma unroll
            for (int mt = 0; mt < 2; mt++)
                #pragma unroll
                for (int q = 0; q < 2; q++) {
                    sS[mt][q] += __shfl_xor_sync(0xffffffffu, sS[mt][q], o);
                    sD[mt][q] += __shfl_xor_sync(0xffffffffu, sD[mt][q], o);
                }
        if (cq == 0) {
            int j = (n0 >> 6) + wn;
            #pragma unroll
            for (int mt = 0; mt < 2; mt++)
                #pragma unroll
                for (int q = 0; q < 2; q++) {
                    int row = m0 + wm * 32 + mt * 16 + r + q * 8;
                    ASP[(size_t)j * M + row] = sS[mt][q];
                    ADP[(size_t)j * M + row] = sD[mt][q];
                }
        }
    }

    #pragma unroll
    for (int mt = 0; mt < 2; mt++) {
        int mrow = m0 + wm * 32 + mt * 16 + r;
        #pragma unroll
        for (int nt = 0; nt < 8; nt++) {
            int ncol = n0 + wn * 64 + nt * 8 + cq * 2;
            float* ac = acc[mt][nt];
            float2 v0 = make_float2(ac[0], ac[1]);
            float2 v1 = make_float2(ac[2], ac[3]);
            if (bias) {
                float b0 = bias[ncol], b1 = bias[ncol + 1];
                v0.x += b0; v0.y += b1; v1.x += b0; v1.y += b1;
            }
            if (ACT == 1) {
                v0.x = fmaxf(v0.x, 0.f); v0.y = fmaxf(v0.y, 0.f);
                v1.x = fmaxf(v1.x, 0.f); v1.y = fmaxf(v1.y, 0.f);
            }
            if (HALF_OUT) {
                __half* Ch = (__half*)Cv;
                *(__half2*)(Ch + (size_t)mrow * ldc + ncol) = __floats2half2_rn(v0.x, v0.y);
                *(__half2*)(Ch + (size_t)(mrow + 8) * ldc + ncol) = __floats2half2_rn(v1.x, v1.y);
            } else {
                float* Cf = (float*)Cv;
                *(float2*)(Cf + (size_t)mrow * ldc + ncol) = v0;
                *(float2*)(Cf + (size_t)(mrow + 8) * ldc + ncol) = v1;
            }
        }
    }
}

// ---------------- split-K reduce (+bias) ----------------
__global__ void splitk_red_k(const float* __restrict__ part, const float* __restrict__ bias,
                             float* __restrict__ y)
{
    int i = (blockIdx.x * 256 + threadIdx.x) * 4;
    float4 a0 = *(const float4*)(part + i);
    float4 a1 = *(const float4*)(part + (size_t)MTOT * DD + i);
    float4 a2 = *(const float4*)(part + (size_t)2 * MTOT * DD + i);
    float4 a3 = *(const float4*)(part + (size_t)3 * MTOT * DD + i);
    int c = i & (DD - 1);
    float4 b = *(const float4*)(bias + c);
    float4 o;
    o.x = a0.x + a1.x + a2.x + a3.x + b.x;
    o.y = a0.y + a1.y + a2.y + a3.y + b.y;
    o.z = a0.z + a1.z + a2.z + a3.z + b.z;
    o.w = a0.w + a1.w + a2.w + a3.w + b.w;
    *(float4*)(y + i) = o;
}

// ---------------- asad reduce ----------------
__global__ void asad_reduce_k(const float* __restrict__ ASP, const float* __restrict__ ADP,
                              float* __restrict__ as_, float* __restrict__ ad_)
{
    int idx = blockIdx.x * 256 + threadIdx.x;
    int row = idx >> 3, h = idx & 7;
    float s = 0.f, d = 0.f;
    #pragma unroll
    for (int j = 4 * h; j < 4 * h + 4; j++) {
        s += ASP[(size_t)j * MTOT + row];
        d += ADP[(size_t)j * MTOT + row];
    }
    as_[row * 8 + h] = s;
    ad_[row * 8 + h] = d;
}

// ---------------- sparse GAT aggregation (fp16 + HFMA2 accumulation) ----------------
__global__ void __launch_bounds__(256) gat_agg_k(
    const __half* __restrict__ hb, const float* __restrict__ as_,
    const float* __restrict__ ad_, const int* __restrict__ nbr,
    const int* __restrict__ cnt, const float* __restrict__ bias,
    float* __restrict__ y, __half* __restrict__ yh)
{
    __shared__ int    s_nbr[NBCAP];
    __shared__ float  s_alpha[HH][NBCAP];
    __shared__ __half2 s_ah[HH][NBCAP];
    __shared__ float  s_inv[HH];
    __shared__ float  s_red[HH][DD];
    int bt  = blockIdx.x;
    int b   = bt >> 10;
    int tid = threadIdx.x;
    int nc  = cnt[bt];
    for (int j = tid; j < nc; j += 256) s_nbr[j] = nbr[(size_t)bt * NBCAP + j];
    __syncthreads();

    for (int j = tid; j < nc; j += 256) {
        int s = s_nbr[j];
        const float* ap = as_ + (size_t)(b * NNODE + s) * HH;
        #pragma unroll
        for (int h = 0; h < HH; h++) {
            float e = ad_[bt * HH + h] + ap[h];
            e = e >= 0.f ? e : 0.2f * e;
            s_alpha[h][j] = __expf(e);
        }
    }
    __syncthreads();

    int h    = tid >> 5;
    int lane = tid & 31;
    {
        float sum = 0.f;
        for (int j = lane; j < nc; j += 32) sum += s_alpha[h][j];
        #pragma unroll
        for (int o = 16; o; o >>= 1) sum += __shfl_xor_sync(0xffffffffu, sum, o);
        if (lane == 0) s_inv[h] = 1.f / (8.f * sum);
    }
    __syncthreads();
    for (int j = tid; j < nc; j += 256) {
        #pragma unroll
        for (int hh = 0; hh < HH; hh++) {
            float w = s_alpha[hh][j] * s_inv[hh];
            s_ah[hh][j] = __float2half2_rn(w);
        }
    }
    __syncthreads();

    // gather: lane owns cols [lane*8, lane*8+8) of head h — 1 LDG.128 + 4 HFMA2 per edge
    const __half* hbase = hb + (size_t)b * NNODE * (HH * DD) + h * DD + lane * 8;
    __half2 a2[4];
    #pragma unroll
    for (int i = 0; i < 4; i++) a2[i] = __floats2half2_rn(0.f, 0.f);
    #pragma unroll 2
    for (int j = 0; j < nc; j++) {
        __half2 w2 = s_ah[h][j];
        float4 raw = *(const float4*)(hbase + (size_t)s_nbr[j] * (HH * DD));
        const __half2* h2 = (const __half2*)&raw;
        #pragma unroll
        for (int i = 0; i < 4; i++)
            a2[i] = __hfma2(h2[i], w2, a2[i]);
    }
    {
        float2 f0 = __half22float2(a2[0]);
        float2 f1 = __half22float2(a2[1]);
        float2 f2 = __half22float2(a2[2]);
        float2 f3 = __half22float2(a2[3]);
        *(float4*)&s_red[h][lane * 8]     = make_float4(f0.x, f0.y, f1.x, f1.y);
        *(float4*)&s_red[h][lane * 8 + 4] = make_float4(f2.x, f2.y, f3.x, f3.y);
    }
    __syncthreads();

    {
        int c = tid;
        float v = bias[c];
        #pragma unroll
        for (int hh = 0; hh < HH; hh++) v += s_red[hh][c];
        y[(size_t)bt * DD + c] = v;
        yh[(size_t)bt * DD + c] = __float2half_rn(v);
    }
}

// ---------------- sparse masked attention: two-pass (R11) ----------------
__global__ void __launch_bounds__(256) attn_sparse_k(
    const __half* __restrict__ QKV, const int* __restrict__ nbr,
    const int* __restrict__ cnt, __half* __restrict__ Om)
{
    __shared__ int   s_nbr[NBCAP];
    __shared__ float s_w[HH][NBCAP];
    __shared__ float s_winv[HH];
    int bt  = blockIdx.x;
    int b   = bt >> 10;
    int tid = threadIdx.x;
    int nc  = cnt[bt];
    for (int j = tid; j < nc; j += 256) s_nbr[j] = nbr[(size_t)bt * NBCAP + j];
    __syncthreads();
    int h = tid >> 5, lane = tid & 31;
    const int LD3 = 3 * DD;

    unsigned qh[16];
    {
        const uint4* qp = (const uint4*)(QKV + (size_t)bt * LD3 + h * DHH);
        const __half2 sc2 = __floats2half2_rn(0.17677669529663687f, 0.17677669529663687f);
        #pragma unroll
        for (int i = 0; i < 4; i++) {
            uint4 v = qp[i];
            unsigned* u = (unsigned*)&v;
            #pragma unroll
            for (int k = 0; k < 4; k++) {
                __half2 hv = __hmul2(*(__half2*)&u[k], sc2);
                qh[i * 4 + k] = *(unsigned*)&hv;
            }
        }
    }

    float aw = 0.f;
    for (int j = lane; j < nc; j += 32) {
        int s = s_nbr[j];
        const uint4* kp = (const uint4*)(QKV + (size_t)(b * NNODE + s) * LD3 + DD + h * DHH);
        __half2 acc2 = __floats2half2_rn(0.f, 0.f);
        #pragma unroll
        for (int i = 0; i < 4; i++) {
            uint4 v = kp[i];
            unsigned* u = (unsigned*)&v;
            #pragma unroll
            for (int k = 0; k < 4; k++)
                acc2 = __hfma2(*(__half2*)&u[k], *(__half2*)&qh[i * 4 + k], acc2);
        }
        float2 f = __half22float2(acc2);
        float w = __expf(f.x + f.y);
        s_w[h][j] = w;
        aw += w;
    }
    #pragma unroll
    for (int o = 16; o; o >>= 1) aw += __shfl_xor_sync(0xffffffffu, aw, o);
    if (lane == 0) s_winv[h] = 1.f / aw;
    __syncwarp();

    const __half* vbase = QKV + (size_t)b * NNODE * LD3 + 2 * DD + h * DHH + lane;
    float accv = 0.f;
    int j = 0;
    for (; j + 4 <= nc; j += 4) {
        #pragma unroll
        for (int u = 0; u < 4; u++) {
            int s = s_nbr[j + u];
            accv = fmaf(s_w[h][j + u], __half2float(vbase[(size_t)s * LD3]), accv);
        }
    }
    for (; j < nc; j++) {
        int s = s_nbr[j];
        accv = fmaf(s_w[h][j], __half2float(vbase[(size_t)s * LD3]), accv);
    }
    Om[(size_t)bt * DD + h * DHH + lane] = __float2half_rn(accv * s_winv[h]);
}

// ---------------- layernorm: warp per row ----------------
template<int MODE, int WRITEH>
__global__ void __launch_bounds__(256) ln_warp_k(
    const float* __restrict__ a, const float* __restrict__ bsrc,
    const float* __restrict__ gam, const float* __restrict__ bet,
    float* __restrict__ out, __half* __restrict__ outh)
{
    int row  = blockIdx.x * 8 + (threadIdx.x >> 5);
    int lane = threadIdx.x & 31;
    size_t base = (size_t)row * DD;
    float v[8];
    float sum = 0.f;
    #pragma unroll
    for (int p = 0; p < 2; p++) {
        int c = lane * 4 + p * 128;
        float4 av = *(const float4*)(a + base + c);
        float4 bv = *(const float4*)(bsrc + base + c);
        if (MODE == 1) {
            bv.x = fmaxf(bv.x, 0.f); bv.y = fmaxf(bv.y, 0.f);
            bv.z = fmaxf(bv.z, 0.f); bv.w = fmaxf(bv.w, 0.f);
        }
        v[p*4+0] = av.x + bv.x; v[p*4+1] = av.y + bv.y;
        v[p*4+2] = av.z + bv.z; v[p*4+3] = av.w + bv.w;
        sum += v[p*4+0] + v[p*4+1] + v[p*4+2] + v[p*4+3];
    }
    #pragma unroll
    for (int o = 16; o; o >>= 1) sum += __shfl_xor_sync(0xffffffffu, sum, o);
    float mean = sum * (1.f / DD);
    float var = 0.f;
    #pragma unroll
    for (int i = 0; i < 8; i++) { float d = v[i] - mean; var += d * d; }
    #pragma unroll
    for (int o = 16; o; o >>= 1) var += __shfl_xor_sync(0xffffffffu, var, o);
    float rstd = rsqrtf(var * (1.f / DD) + 1e-5f);
    #pragma unroll
    for (int p = 0; p < 2; p++) {
        int c = lane * 4 + p * 128;
        float4 g = *(const float4*)(gam + c);
        float4 bb = *(const float4*)(bet + c);
        float4 o4;
        o4.x = (v[p*4+0] - mean) * rstd * g.x + bb.x;
        o4.y = (v[p*4+1] - mean) * rstd * g.y + bb.y;
        o4.z = (v[p*4+2] - mean) * rstd * g.z + bb.z;
        o4.w = (v[p*4+3] - mean) * rstd * g.w + bb.w;
        *(float4*)(out + base + c) = o4;
        if (WRITEH) {
            __half2 h0 = __floats2half2_rn(o4.x, o4.y);
            __half2 h1 = __floats2half2_rn(o4.z, o4.w);
            *(uint2*)(outh + base + c) = make_uint2(*(unsigned*)&h0, *(unsigned*)&h1);
        }
    }
}

extern "C" void kernel_launch(void* const* d_in, const int* in_sizes, int n_in,
                              void* d_out, int out_size)
{
    const float* emb  = (const float*)d_in[0];
    const int*   mask = (const int*)  d_in[2];
    const float* gatW = (const float*)d_in[4];
    const float* attS = (const float*)d_in[5];
    const float* attD = (const float*)d_in[6];
    const float* gatB = (const float*)d_in[7];
    const float* glnS = (const float*)d_in[8];
    const float* glnB = (const float*)d_in[9];
    const float* Wq = (const float*)d_in[10], *bq = (const float*)d_in[11];
    const float* Wk = (const float*)d_in[12], *bk = (const float*)d_in[13];
    const float* Wv = (const float*)d_in[14], *bv = (const float*)d_in[15];
    const float* Wo = (const float*)d_in[16], *bo = (const float*)d_in[17];
    const float* W1 = (const float*)d_in[18], *b1 = (const float*)d_in[19];
    const float* W2 = (const float*)d_in[20], *b2 = (const float*)d_in[21];
    const float* l1s = (const float*)d_in[22], *l1b = (const float*)d_in[23];
    const float* l2s = (const float*)d_in[24], *l2b = (const float*)d_in[25];
    float* out = (float*)d_out;

    float *XC,*AS,*AD,*ASP,*ADP,*BQKV,*Y,*PART;
    __half *XCH,*EMBH,*HBH,*QKVH,*WQKVH,*GATWH,*WOH,*W1H,*W2H,*AOH,*YH,*FFH;
    unsigned* BITS; int *NBR,*CNT;
    cudaGetSymbolAddress((void**)&XC, g_XC);
    cudaGetSymbolAddress((void**)&XCH, g_XCH);
    cudaGetSymbolAddress((void**)&EMBH, g_EMBH);
    cudaGetSymbolAddress((void**)&HBH, g_HBH);
    cudaGetSymbolAddress((void**)&AS, g_AS);
    cudaGetSymbolAddress((void**)&AD, g_AD);
    cudaGetSymbolAddress((void**)&ASP, g_ASP);
    cudaGetSymbolAddress((void**)&ADP, g_ADP);
    cudaGetSymbolAddress((void**)&QKVH, g_QKVH);
    cudaGetSymbolAddress((void**)&WQKVH, g_WQKVH);
    cudaGetSymbolAddress((void**)&BQKV, g_BQKV);
    cudaGetSymbolAddress((void**)&GATWH, g_GATWH);
    cudaGetSymbolAddress((void**)&WOH, g_WOH);
    cudaGetSymbolAddress((void**)&W1H, g_W1H);
    cudaGetSymbolAddress((void**)&W2H, g_W2H);
    cudaGetSymbolAddress((void**)&AOH, g_AOH);
    cudaGetSymbolAddress((void**)&Y,  g_Y);
    cudaGetSymbolAddress((void**)&YH, g_YH);
    cudaGetSymbolAddress((void**)&FFH, g_FFH);
    cudaGetSymbolAddress((void**)&PART, g_PART);
    cudaGetSymbolAddress((void**)&BITS, g_BITS);
    cudaGetSymbolAddress((void**)&NBR, g_NBR);
    cudaGetSymbolAddress((void**)&CNT, g_CNT);

    const int M = MTOT;

    pack_adj_k<<<(BB*32*NNODE)/256, 256>>>(mask, BITS);
    build_nbr_k<<<(MTOT)/256, 256>>>(BITS, NBR, CNT);
    pack_qkv_k<<<(LTN*DD*3*DD + 255)/256, 256>>>(Wq, Wk, Wv, bq, bk, bv, WQKVH, BQKV);
    cvt_all_k<<<(CV_TOT/4 + 255)/256, 256>>>(emb, gatW, Wo, W1, W2);

    // ---- GAT stack ----
    const __half* x = EMBH;
    for (int l = 0; l < LGN; l++) {
        hgemm_k<true,0,1,1,1><<<dim3((HH*DD)/128, M/128), 256>>>(
            M, HH*DD, DD, x, DD, GATWH + (size_t)l*HH*DD*DD, DD,
            HBH, HH*DD, nullptr, attS + l*HH*DD, attD + l*HH*DD, ASP, ADP);
        asad_reduce_k<<<(MTOT*8)/256, 256>>>(ASP, ADP, AS, AD);
        gat_agg_k<<<M, 256>>>(HBH, AS, AD, NBR, CNT, gatB + l*DD, Y, YH);
        x = YH;
    }
    ln_warp_k<1,1><<<M/8, 256>>>(emb, Y, glnS, glnB, XC, XCH);

    // ---- transformer layers ----
    for (int l = 0; l < LTN; l++) {
        hgemm_k<false,0,1,0,1><<<dim3((3*DD)/128, M/128), 256>>>(
            M, 3*DD, DD, XCH, DD, WQKVH + (size_t)l*DD*3*DD, 3*DD, QKVH, 3*DD,
            BQKV + l*3*DD, nullptr, nullptr, nullptr, nullptr);
        attn_sparse_k<<<M, 256>>>(QKVH, NBR, CNT, AOH);
        hgemm_k<false,0,0,0,1><<<dim3(DD/128, M/128), 256>>>(
            M, DD, DD, AOH, DD, WOH + (size_t)l*DD*DD, DD, Y, DD,
            bo + l*DD, nullptr, nullptr, nullptr, nullptr);
        ln_warp_k<0,1><<<M/8, 256>>>(XC, Y, l1s + l*DD, l1b + l*DD, XC, XCH);
        hgemm_k<false,1,1,0,1><<<dim3(DFFX/128, M/128), 256>>>(
            M, DFFX, DD, XCH, DD, W1H + (size_t)l*DD*DFFX, DFFX, FFH, DFFX,
            b1 + l*DFFX, nullptr, nullptr, nullptr, nullptr);
        // FFN2: split-K=4 into PART, then reduce(+bias) into Y
        hgemm_k<false,0,0,0,SPLK><<<dim3(DD/128, M/128, SPLK), 256>>>(
            M, DD, DFFX, FFH, DFFX, W2H + (size_t)l*DFFX*DD, DD, PART, DD,
            nullptr, nullptr, nullptr, nullptr, nullptr);
        splitk_red_k<<<(MTOT*DD/4)/256, 256>>>(PART, b2 + l*DD, Y);
        if (l == LTN - 1)
            ln_warp_k<0,0><<<M/8, 256>>>(XC, Y, l2s + l*DD, l2b + l*DD, out, nullptr);
        else
            ln_warp_k<0,1><<<M/8, 256>>>(XC, Y, l2s + l*DD, l2b + l*DD, XC, XCH);
    }
}

// round 13
// speedup vs baseline: 1.3874x; 1.0383x over previous
#include <cuda_runtime.h>
#include <cuda_fp16.h>
#include <math.h>

// ---------------- dims ----------------
#define BB    8
#define NNODE 1024
#define DD    256
#define HH    8
#define DHH   32
#define DFFX  1024
#define LGN   2
#define LTN   2
#define NBCAP 256
#define MTOT  (BB*NNODE)
#define SPLK  4

// ---------------- scratch (device globals; no runtime allocation) ----------------
__device__ float                 g_XC[MTOT*DD];
__device__ __align__(16) __half  g_XCH[MTOT*DD];
__device__ __align__(16) __half  g_EMBH[MTOT*DD];
__device__ __align__(16) __half  g_HBH[MTOT*HH*DD];
__device__ float                 g_AS[MTOT*HH];
__device__ float                 g_AD[MTOT*HH];
__device__ float                 g_ASP[32*MTOT];
__device__ float                 g_ADP[32*MTOT];
__device__ __align__(16) __half  g_QKVH[MTOT*3*DD];
__device__ __align__(16) __half  g_WQKVH[LTN*DD*3*DD];
__device__ float                 g_BQKV[LTN*3*DD];
__device__ __align__(16) __half  g_GATWH[LGN*HH*DD*DD];
__device__ __align__(16) __half  g_WOH[LTN*DD*DD];
__device__ __align__(16) __half  g_W1H[LTN*DD*DFFX];
__device__ __align__(16) __half  g_W2H[LTN*DFFX*DD];
__device__ __align__(16) __half  g_AOH[MTOT*DD];
__device__ float                 g_Y [MTOT*DD];
__device__ __align__(16) __half  g_YH[MTOT*DD];
__device__ __align__(16) __half  g_FFH[MTOT*DFFX];
__device__ float                 g_PART[SPLK*MTOT*DD];
__device__ unsigned              g_BITS[MTOT*(NNODE/32)];
__device__ int                   g_NBR[MTOT*NBCAP];
__device__ int                   g_CNT[MTOT];

// ---------------- helpers ----------------
__device__ __forceinline__ void mma_f16(float* c, const unsigned* a, const unsigned* b) {
    asm volatile(
        "mma.sync.aligned.m16n8k16.row.col.f32.f16.f16.f32 "
        "{%0,%1,%2,%3}, {%4,%5,%6,%7}, {%8,%9}, {%0,%1,%2,%3};\n"
        : "+f"(c[0]), "+f"(c[1]), "+f"(c[2]), "+f"(c[3])
        : "r"(a[0]), "r"(a[1]), "r"(a[2]), "r"(a[3]), "r"(b[0]), "r"(b[1]));
}

__device__ __forceinline__ unsigned saddr(const void* p) {
    return (unsigned)__cvta_generic_to_shared(p);
}
__device__ __forceinline__ void cp16(unsigned dst, const void* src) {
    asm volatile("cp.async.cg.shared.global [%0], [%1], 16;\n" :: "r"(dst), "l"(src));
}
__device__ __forceinline__ void cp_commit() {
    asm volatile("cp.async.commit_group;\n" ::: "memory");
}
template<int N>
__device__ __forceinline__ void cp_wait() {
    asm volatile("cp.async.wait_group %0;\n" :: "n"(N) : "memory");
}
__device__ __forceinline__ void ldsm4(unsigned& r0, unsigned& r1, unsigned& r2, unsigned& r3,
                                      unsigned addr) {
    asm volatile("ldmatrix.sync.aligned.m8n8.x4.shared.b16 {%0,%1,%2,%3}, [%4];"
                 : "=r"(r0), "=r"(r1), "=r"(r2), "=r"(r3) : "r"(addr));
}
__device__ __forceinline__ void ldsm4t(unsigned& r0, unsigned& r1, unsigned& r2, unsigned& r3,
                                       unsigned addr) {
    asm volatile("ldmatrix.sync.aligned.m8n8.x4.trans.shared.b16 {%0,%1,%2,%3}, [%4];"
                 : "=r"(r0), "=r"(r1), "=r"(r2), "=r"(r3) : "r"(addr));
}

// ---------------- adjacency pack ----------------
__global__ void pack_adj_k(const int* __restrict__ mask, unsigned* __restrict__ bits) {
    int idx = blockIdx.x * blockDim.x + threadIdx.x;
    int t  = idx & (NNODE - 1);
    int sw = (idx >> 10) & 31;
    int b  = idx >> 15;
    const int* mp = mask + ((size_t)b * NNODE + (size_t)sw * 32) * NNODE + t;
    unsigned w = 0;
    #pragma unroll
    for (int i = 0; i < 32; i++)
        if (mp[(size_t)i * NNODE] > 0) w |= (1u << i);
    int s0 = sw * 32;
    if (t >= s0 && t < s0 + 32) w |= (1u << (t - s0));
    bits[(b * NNODE + t) * 32 + sw] = w;
}

// ---------------- neighbor list build ----------------
__global__ void build_nbr_k(const unsigned* __restrict__ bits,
                            int* __restrict__ nbr, int* __restrict__ cnt) {
    int bt = blockIdx.x * blockDim.x + threadIdx.x;
    if (bt >= MTOT) return;
    const unsigned* bw = bits + (size_t)bt * 32;
    int* np = nbr + (size_t)bt * NBCAP;
    int c = 0;
    #pragma unroll 4
    for (int w = 0; w < 32; w++) {
        unsigned m = bw[w];
        while (m) {
            int bit = __ffs(m) - 1;
            m &= m - 1;
            if (c < NBCAP) np[c] = w * 32 + bit;
            c++;
        }
    }
    cnt[bt] = c < NBCAP ? c : NBCAP;
}

// ---------------- fused fp32 -> fp16 convert of all weights + emb ----------------
#define CV_N1 (MTOT*DD)
#define CV_N2 (LGN*HH*DD*DD)
#define CV_N3 (LTN*DD*DD)
#define CV_N4 (LTN*DD*DFFX)
#define CV_N5 (LTN*DFFX*DD)
#define CV_TOT (CV_N1+CV_N2+CV_N3+CV_N4+CV_N5)

__global__ void cvt_all_k(const float* __restrict__ emb, const float* __restrict__ gatW,
                          const float* __restrict__ Wo, const float* __restrict__ W1,
                          const float* __restrict__ W2)
{
    int i = (blockIdx.x * 256 + threadIdx.x) * 4;
    if (i >= CV_TOT) return;
    const float* src; __half* dst; int off;
    if (i < CV_N1)                         { src = emb;  dst = g_EMBH;  off = i; }
    else if (i < CV_N1 + CV_N2)            { src = gatW; dst = g_GATWH; off = i - CV_N1; }
    else if (i < CV_N1 + CV_N2 + CV_N3)    { src = Wo;   dst = g_WOH;   off = i - CV_N1 - CV_N2; }
    else if (i < CV_N1 + CV_N2 + CV_N3 + CV_N4)
                                           { src = W1;   dst = g_W1H;   off = i - CV_N1 - CV_N2 - CV_N3; }
    else                                   { src = W2;   dst = g_W2H;   off = i - CV_N1 - CV_N2 - CV_N3 - CV_N4; }
    float4 v = *(const float4*)(src + off);
    *(__half2*)(dst + off)     = __floats2half2_rn(v.x, v.y);
    *(__half2*)(dst + off + 2) = __floats2half2_rn(v.z, v.w);
}

// ---------------- QKV pack ----------------
__global__ void pack_qkv_k(const float* __restrict__ Wq, const float* __restrict__ Wk,
                           const float* __restrict__ Wv, const float* __restrict__ bq,
                           const float* __restrict__ bk, const float* __restrict__ bv,
                           __half* __restrict__ W, float* __restrict__ Bb)
{
    int idx = blockIdx.x * 256 + threadIdx.x;
    if (idx >= LTN * DD * 3 * DD) return;
    int n = idx % (3 * DD);
    int k = (idx / (3 * DD)) % DD;
    int l = idx / (3 * DD * DD);
    float v;
    if (n < DD)            v = Wq[((size_t)l * DD + k) * DD + n];
    else if (n < 2 * DD)   v = Wk[((size_t)l * DD + k) * DD + n - DD];
    else                   v = Wv[((size_t)l * DD + k) * DD + n - 2 * DD];
    W[idx] = __float2half_rn(v);
    if (k == 0) {
        float bvv;
        if (n < DD)          bvv = bq[l * DD + n];
        else if (n < 2 * DD) bvv = bk[l * DD + n - DD];
        else                 bvv = bv[l * DD + n - 2 * DD];
        Bb[l * 3 * DD + n] = bvv;
    }
}

// ---------------- fp16 tensor-core GEMM: 2-stage cp.async + ldmatrix ----------------
template<bool BT, int ACT, int HALF_OUT, int ASAD, int SPLITZ>
__global__ void __launch_bounds__(256) hgemm_k(
    int M, int Ncol, int K,
    const __half* __restrict__ A, int lda,
    const __half* __restrict__ B, int ldb,
    void* __restrict__ Cv, int ldc,
    const float* __restrict__ bias,
    const float* __restrict__ attS, const float* __restrict__ attD,
    float* __restrict__ ASP, float* __restrict__ ADP)
{
    if (SPLITZ > 1) {
        int Kc = K / SPLITZ;
        A += (size_t)blockIdx.z * Kc;
        B += (size_t)blockIdx.z * Kc * ldb;
        Cv = (void*)((float*)Cv + (size_t)blockIdx.z * M * Ncol);
        K = Kc;
    }
    __shared__ __align__(16) __half sA[2][128 * 24];
    __shared__ __align__(16) __half sB[2][3072];
    const int tid  = threadIdx.x;
    const int lane = tid & 31, wid = tid >> 5;
    const int wm = wid & 3, wn = wid >> 2;
    const int m0 = blockIdx.y * 128, n0 = blockIdx.x * 128;
    const int r = lane >> 2, cq = lane & 3;

    float acc[2][8][4];
    #pragma unroll
    for (int mt = 0; mt < 2; mt++)
        #pragma unroll
        for (int nt = 0; nt < 8; nt++)
            #pragma unroll
            for (int u = 0; u < 4; u++) acc[mt][nt][u] = 0.f;

    const int T = K / 16;

    auto loadT = [&](int st, int k0) {
        {
            int m = tid >> 1, c = tid & 1;
            cp16(saddr(&sA[st][m * 24 + c * 8]), A + (size_t)(m0 + m) * lda + k0 + c * 8);
        }
        if (BT) {
            int n = tid >> 1, c = tid & 1;
            cp16(saddr(&sB[st][n * 24 + c * 8]), B + (size_t)(n0 + n) * ldb + k0 + c * 8);
        } else {
            int kk = tid >> 4, c = tid & 15;
            cp16(saddr(&sB[st][kk * 136 + c * 8]), B + (size_t)(k0 + kk) * ldb + n0 + c * 8);
        }
        cp_commit();
    };

    loadT(0, 0);
    for (int t = 0; t < T; t++) {
        if (t + 1 < T) { loadT((t + 1) & 1, (t + 1) * 16); cp_wait<1>(); }
        else           { cp_wait<0>(); }
        __syncthreads();
        const int st = t & 1;

        unsigned af[2][4], bf[8][2];
        #pragma unroll
        for (int mt = 0; mt < 2; mt++) {
            int mrow = wm * 32 + mt * 16;
            unsigned addr = saddr(&sA[st][(mrow + (lane & 15)) * 24 + (lane >> 4) * 8]);
            ldsm4(af[mt][0], af[mt][1], af[mt][2], af[mt][3], addr);
        }
        #pragma unroll
        for (int p = 0; p < 4; p++) {
            int nb = wn * 64 + p * 16;
            if (BT) {
                int row = nb + (lane & 7) + ((lane >> 4) << 3);
                int col = ((lane >> 3) & 1) * 8;
                unsigned addr = saddr(&sB[st][row * 24 + col]);
                ldsm4(bf[2 * p][0], bf[2 * p][1], bf[2 * p + 1][0], bf[2 * p + 1][1], addr);
            } else {
                int krow = (lane & 7) + (((lane >> 3) & 1) << 3);
                int coln = nb + (lane >> 4) * 8;
                unsigned addr = saddr(&sB[st][krow * 136 + coln]);
                ldsm4t(bf[2 * p][0], bf[2 * p][1], bf[2 * p + 1][0], bf[2 * p + 1][1], addr);
            }
        }
        #pragma unroll
        for (int mt = 0; mt < 2; mt++)
            #pragma unroll
            for (int nt = 0; nt < 8; nt++)
                mma_f16(acc[mt][nt], af[mt], bf[nt]);
        __syncthreads();
    }

    if (ASAD) {
        float sS[2][2] = {{0,0},{0,0}}, sD[2][2] = {{0,0},{0,0}};
        #pragma unroll
        for (int mt = 0; mt < 2; mt++)
            #pragma unroll
            for (int nt = 0; nt < 8; nt++)
                #pragma unroll
                for (int u = 0; u < 4; u++) {
                    int g = n0 + wn * 64 + nt * 8 + cq * 2 + (u & 1);
                    float v = acc[mt][nt][u];
                    sS[mt][u >> 1] += v * attS[g];
                    sD[mt][u >> 1] += v * attD[g];
                }
        #pragma unroll
        for (int o = 1; o <= 2; o <<= 1)
            #pragma unroll
            for (int mt = 0; mt < 2; mt++)
                #pragma unroll
                for (int q = 0; q < 2; q++) {
                    sS[mt][q] += __shfl_xor_sync(0xffffffffu, sS[mt][q], o);
                    sD[mt][q] += __shfl_xor_sync(0xffffffffu, sD[mt][q], o);
                }
        if (cq == 0) {
            int j = (n0 >> 6) + wn;
            #pragma unroll
            for (int mt = 0; mt < 2; mt++)
                #pragma unroll
                for (int q = 0; q < 2; q++) {
                    int row = m0 + wm * 32 + mt * 16 + r + q * 8;
                    ASP[(size_t)j * M + row] = sS[mt][q];
                    ADP[(size_t)j * M + row] = sD[mt][q];
                }
        }
    }

    #pragma unroll
    for (int mt = 0; mt < 2; mt++) {
        int mrow = m0 + wm * 32 + mt * 16 + r;
        #pragma unroll
        for (int nt = 0; nt < 8; nt++) {
            int ncol = n0 + wn * 64 + nt * 8 + cq * 2;
            float* ac = acc[mt][nt];
            float2 v0 = make_float2(ac[0], ac[1]);
            float2 v1 = make_float2(ac[2], ac[3]);
            if (bias) {
                float b0 = bias[ncol], b1 = bias[ncol + 1];
                v0.x += b0; v0.y += b1; v1.x += b0; v1.y += b1;
            }
            if (ACT == 1) {
                v0.x = fmaxf(v0.x, 0.f); v0.y = fmaxf(v0.y, 0.f);
                v1.x = fmaxf(v1.x, 0.f); v1.y = fmaxf(v1.y, 0.f);
            }
            if (HALF_OUT) {
                __half* Ch = (__half*)Cv;
                *(__half2*)(Ch + (size_t)mrow * ldc + ncol) = __floats2half2_rn(v0.x, v0.y);
                *(__half2*)(Ch + (size_t)(mrow + 8) * ldc + ncol) = __floats2half2_rn(v1.x, v1.y);
            } else {
                float* Cf = (float*)Cv;
                *(float2*)(Cf + (size_t)mrow * ldc + ncol) = v0;
                *(float2*)(Cf + (size_t)(mrow + 8) * ldc + ncol) = v1;
            }
        }
    }
}

// ---------------- asad reduce ----------------
__global__ void asad_reduce_k(const float* __restrict__ ASP, const float* __restrict__ ADP,
                              float* __restrict__ as_, float* __restrict__ ad_)
{
    int idx = blockIdx.x * 256 + threadIdx.x;
    int row = idx >> 3, h = idx & 7;
    float s = 0.f, d = 0.f;
    #pragma unroll
    for (int j = 4 * h; j < 4 * h + 4; j++) {
        s += ASP[(size_t)j * MTOT + row];
        d += ADP[(size_t)j * MTOT + row];
    }
    as_[row * 8 + h] = s;
    ad_[row * 8 + h] = d;
}

// ---------------- sparse GAT aggregation (fp16, HFMA2, 2 accumulator banks) ----------------
__global__ void __launch_bounds__(256) gat_agg_k(
    const __half* __restrict__ hb, const float* __restrict__ as_,
    const float* __restrict__ ad_, const int* __restrict__ nbr,
    const int* __restrict__ cnt, const float* __restrict__ bias,
    float* __restrict__ y, __half* __restrict__ yh)
{
    __shared__ int    s_nbr[NBCAP];
    __shared__ float  s_alpha[HH][NBCAP];
    __shared__ __half2 s_ah[HH][NBCAP];
    __shared__ float  s_inv[HH];
    __shared__ float  s_red[HH][DD];
    int bt  = blockIdx.x;
    int b   = bt >> 10;
    int tid = threadIdx.x;
    int nc  = cnt[bt];
    for (int j = tid; j < nc; j += 256) s_nbr[j] = nbr[(size_t)bt * NBCAP + j];
    __syncthreads();

    for (int j = tid; j < nc; j += 256) {
        int s = s_nbr[j];
        const float* ap = as_ + (size_t)(b * NNODE + s) * HH;
        #pragma unroll
        for (int h = 0; h < HH; h++) {
            float e = ad_[bt * HH + h] + ap[h];
            e = e >= 0.f ? e : 0.2f * e;
            s_alpha[h][j] = __expf(e);
        }
    }
    __syncthreads();

    int h    = tid >> 5;
    int lane = tid & 31;
    {
        float sum = 0.f;
        for (int j = lane; j < nc; j += 32) sum += s_alpha[h][j];
        #pragma unroll
        for (int o = 16; o; o >>= 1) sum += __shfl_xor_sync(0xffffffffu, sum, o);
        if (lane == 0) s_inv[h] = 1.f / (8.f * sum);
    }
    __syncthreads();
    for (int j = tid; j < nc; j += 256) {
        #pragma unroll
        for (int hh = 0; hh < HH; hh++) {
            float w = s_alpha[hh][j] * s_inv[hh];
            s_ah[hh][j] = __float2half2_rn(w);
        }
    }
    __syncthreads();

    // gather: 2 edges/iter into 2 independent half2 accumulator banks
    const __half* hbase = hb + (size_t)b * NNODE * (HH * DD) + h * DD + lane * 8;
    __half2 acc0[4], acc1[4];
    #pragma unroll
    for (int i = 0; i < 4; i++) {
        acc0[i] = __floats2half2_rn(0.f, 0.f);
        acc1[i] = __floats2half2_rn(0.f, 0.f);
    }
    int j = 0;
    for (; j + 2 <= nc; j += 2) {
        __half2 w0 = s_ah[h][j];
        __half2 w1 = s_ah[h][j + 1];
        float4 r0 = *(const float4*)(hbase + (size_t)s_nbr[j] * (HH * DD));
        float4 r1 = *(const float4*)(hbase + (size_t)s_nbr[j + 1] * (HH * DD));
        const __half2* p0 = (const __half2*)&r0;
        const __half2* p1 = (const __half2*)&r1;
        #pragma unroll
        for (int i = 0; i < 4; i++) {
            acc0[i] = __hfma2(p0[i], w0, acc0[i]);
            acc1[i] = __hfma2(p1[i], w1, acc1[i]);
        }
    }
    if (j < nc) {
        __half2 w0 = s_ah[h][j];
        float4 r0 = *(const float4*)(hbase + (size_t)s_nbr[j] * (HH * DD));
        const __half2* p0 = (const __half2*)&r0;
        #pragma unroll
        for (int i = 0; i < 4; i++)
            acc0[i] = __hfma2(p0[i], w0, acc0[i]);
    }
    {
        #pragma unroll
        for (int i = 0; i < 2; i++) {
            float2 a0 = __half22float2(acc0[2*i]),   b0 = __half22float2(acc1[2*i]);
            float2 a1 = __half22float2(acc0[2*i+1]), b1 = __half22float2(acc1[2*i+1]);
            *(float4*)&s_red[h][lane * 8 + 4*i] =
                make_float4(a0.x + b0.x, a0.y + b0.y, a1.x + b1.x, a1.y + b1.y);
        }
    }
    __syncthreads();

    {
        int c = tid;
        float v = bias[c];
        #pragma unroll
        for (int hh = 0; hh < HH; hh++) v += s_red[hh][c];
        y[(size_t)bt * DD + c] = v;
        yh[(size_t)bt * DD + c] = __float2half_rn(v);
    }
}

// ---------------- sparse masked attention: two-pass, ILP pass 2 ----------------
__global__ void __launch_bounds__(256) attn_sparse_k(
    const __half* __restrict__ QKV, const int* __restrict__ nbr,
    const int* __restrict__ cnt, __half* __restrict__ Om)
{
    __shared__ int   s_nbr[NBCAP];
    __shared__ float s_w[HH][NBCAP];
    __shared__ float s_winv[HH];
    int bt  = blockIdx.x;
    int b   = bt >> 10;
    int tid = threadIdx.x;
    int nc  = cnt[bt];
    for (int j = tid; j < nc; j += 256) s_nbr[j] = nbr[(size_t)bt * NBCAP + j];
    __syncthreads();
    int h = tid >> 5, lane = tid & 31;
    const int LD3 = 3 * DD;

    unsigned qh[16];
    {
        const uint4* qp = (const uint4*)(QKV + (size_t)bt * LD3 + h * DHH);
        const __half2 sc2 = __floats2half2_rn(0.17677669529663687f, 0.17677669529663687f);
        #pragma unroll
        for (int i = 0; i < 4; i++) {
            uint4 v = qp[i];
            unsigned* u = (unsigned*)&v;
            #pragma unroll
            for (int k = 0; k < 4; k++) {
                __half2 hv = __hmul2(*(__half2*)&u[k], sc2);
                qh[i * 4 + k] = *(unsigned*)&hv;
            }
        }
    }

    float aw = 0.f;
    for (int j = lane; j < nc; j += 32) {
        int s = s_nbr[j];
        const uint4* kp = (const uint4*)(QKV + (size_t)(b * NNODE + s) * LD3 + DD + h * DHH);
        __half2 acc2 = __floats2half2_rn(0.f, 0.f);
        #pragma unroll
        for (int i = 0; i < 4; i++) {
            uint4 v = kp[i];
            unsigned* u = (unsigned*)&v;
            #pragma unroll
            for (int k = 0; k < 4; k++)
                acc2 = __hfma2(*(__half2*)&u[k], *(__half2*)&qh[i * 4 + k], acc2);
        }
        float2 f = __half22float2(acc2);
        float w = __expf(f.x + f.y);
        s_w[h][j] = w;
        aw += w;
    }
    #pragma unroll
    for (int o = 16; o; o >>= 1) aw += __shfl_xor_sync(0xffffffffu, aw, o);
    if (lane == 0) s_winv[h] = 1.f / aw;
    __syncwarp();

    // pass 2: 4 independent fp32 accumulators
    const __half* vbase = QKV + (size_t)b * NNODE * LD3 + 2 * DD + h * DHH + lane;
    float av0 = 0.f, av1 = 0.f, av2 = 0.f, av3 = 0.f;
    int j = 0;
    for (; j + 4 <= nc; j += 4) {
        av0 = fmaf(s_w[h][j],     __half2float(vbase[(size_t)s_nbr[j]     * LD3]), av0);
        av1 = fmaf(s_w[h][j + 1], __half2float(vbase[(size_t)s_nbr[j + 1] * LD3]), av1);
        av2 = fmaf(s_w[h][j + 2], __half2float(vbase[(size_t)s_nbr[j + 2] * LD3]), av2);
        av3 = fmaf(s_w[h][j + 3], __half2float(vbase[(size_t)s_nbr[j + 3] * LD3]), av3);
    }
    for (; j < nc; j++)
        av0 = fmaf(s_w[h][j], __half2float(vbase[(size_t)s_nbr[j] * LD3]), av0);
    float accv = (av0 + av1) + (av2 + av3);
    Om[(size_t)bt * DD + h * DHH + lane] = __float2half_rn(accv * s_winv[h]);
}

// ---------------- layernorm: warp per row ----------------
// MODE 0: out = LN(a + bsrc)          MODE 1: out = LN(a + relu(bsrc))
// MODE 2: out = LN(a + sum4(bsrc as PART slices) + bias2)
template<int MODE, int WRITEH>
__global__ void __launch_bounds__(256) ln_warp_k(
    const float* __restrict__ a, const float* __restrict__ bsrc,
    const float* __restrict__ gam, const float* __restrict__ bet,
    float* __restrict__ out, __half* __restrict__ outh,
    const float* __restrict__ bias2)
{
    int row  = blockIdx.x * 8 + (threadIdx.x >> 5);
    int lane = threadIdx.x & 31;
    size_t base = (size_t)row * DD;
    float v[8];
    float sum = 0.f;
    #pragma unroll
    for (int p = 0; p < 2; p++) {
        int c = lane * 4 + p * 128;
        float4 av = *(const float4*)(a + base + c);
        float4 bv;
        if (MODE == 2) {
            float4 p0 = *(const float4*)(bsrc + base + c);
            float4 p1 = *(const float4*)(bsrc + (size_t)MTOT * DD + base + c);
            float4 p2 = *(const float4*)(bsrc + (size_t)2 * MTOT * DD + base + c);
            float4 p3 = *(const float4*)(bsrc + (size_t)3 * MTOT * DD + base + c);
            float4 bb2 = *(const float4*)(bias2 + c);
            bv.x = p0.x + p1.x + p2.x + p3.x + bb2.x;
            bv.y = p0.y + p1.y + p2.y + p3.y + bb2.y;
            bv.z = p0.z + p1.z + p2.z + p3.z + bb2.z;
            bv.w = p0.w + p1.w + p2.w + p3.w + bb2.w;
        } else {
            bv = *(const float4*)(bsrc + base + c);
            if (MODE == 1) {
                bv.x = fmaxf(bv.x, 0.f); bv.y = fmaxf(bv.y, 0.f);
                bv.z = fmaxf(bv.z, 0.f); bv.w = fmaxf(bv.w, 0.f);
            }
        }
        v[p*4+0] = av.x + bv.x; v[p*4+1] = av.y + bv.y;
        v[p*4+2] = av.z + bv.z; v[p*4+3] = av.w + bv.w;
        sum += v[p*4+0] + v[p*4+1] + v[p*4+2] + v[p*4+3];
    }
    #pragma unroll
    for (int o = 16; o; o >>= 1) sum += __shfl_xor_sync(0xffffffffu, sum, o);
    float mean = sum * (1.f / DD);
    float var = 0.f;
    #pragma unroll
    for (int i = 0; i < 8; i++) { float d = v[i] - mean; var += d * d; }
    #pragma unroll
    for (int o = 16; o; o >>= 1) var += __shfl_xor_sync(0xffffffffu, var, o);
    float rstd = rsqrtf(var * (1.f / DD) + 1e-5f);
    #pragma unroll
    for (int p = 0; p < 2; p++) {
        int c = lane * 4 + p * 128;
        float4 g = *(const float4*)(gam + c);
        float4 bb = *(const float4*)(bet + c);
        float4 o4;
        o4.x = (v[p*4+0] - mean) * rstd * g.x + bb.x;
        o4.y = (v[p*4+1] - mean) * rstd * g.y + bb.y;
        o4.z = (v[p*4+2] - mean) * rstd * g.z + bb.z;
        o4.w = (v[p*4+3] - mean) * rstd * g.w + bb.w;
        *(float4*)(out + base + c) = o4;
        if (WRITEH) {
            __half2 h0 = __floats2half2_rn(o4.x, o4.y);
            __half2 h1 = __floats2half2_rn(o4.z, o4.w);
            *(uint2*)(outh + base + c) = make_uint2(*(unsigned*)&h0, *(unsigned*)&h1);
        }
    }
}

extern "C" void kernel_launch(void* const* d_in, const int* in_sizes, int n_in,
                              void* d_out, int out_size)
{
    const float* emb  = (const float*)d_in[0];
    const int*   mask = (const int*)  d_in[2];
    const float* gatW = (const float*)d_in[4];
    const float* attS = (const float*)d_in[5];
    const float* attD = (const float*)d_in[6];
    const float* gatB = (const float*)d_in[7];
    const float* glnS = (const float*)d_in[8];
    const float* glnB = (const float*)d_in[9];
    const float* Wq = (const float*)d_in[10], *bq = (const float*)d_in[11];
    const float* Wk = (const float*)d_in[12], *bk = (const float*)d_in[13];
    const float* Wv = (const float*)d_in[14], *bv = (const float*)d_in[15];
    const float* Wo = (const float*)d_in[16], *bo = (const float*)d_in[17];
    const float* W1 = (const float*)d_in[18], *b1 = (const float*)d_in[19];
    const float* W2 = (const float*)d_in[20], *b2 = (const float*)d_in[21];
    const float* l1s = (const float*)d_in[22], *l1b = (const float*)d_in[23];
    const float* l2s = (const float*)d_in[24], *l2b = (const float*)d_in[25];
    float* out = (float*)d_out;

    float *XC,*AS,*AD,*ASP,*ADP,*BQKV,*Y,*PART;
    __half *XCH,*EMBH,*HBH,*QKVH,*WQKVH,*GATWH,*WOH,*W1H,*W2H,*AOH,*YH,*FFH;
    unsigned* BITS; int *NBR,*CNT;
    cudaGetSymbolAddress((void**)&XC, g_XC);
    cudaGetSymbolAddress((void**)&XCH, g_XCH);
    cudaGetSymbolAddress((void**)&EMBH, g_EMBH);
    cudaGetSymbolAddress((void**)&HBH, g_HBH);
    cudaGetSymbolAddress((void**)&AS, g_AS);
    cudaGetSymbolAddress((void**)&AD, g_AD);
    cudaGetSymbolAddress((void**)&ASP, g_ASP);
    cudaGetSymbolAddress((void**)&ADP, g_ADP);
    cudaGetSymbolAddress((void**)&QKVH, g_QKVH);
    cudaGetSymbolAddress((void**)&WQKVH, g_WQKVH);
    cudaGetSymbolAddress((void**)&BQKV, g_BQKV);
    cudaGetSymbolAddress((void**)&GATWH, g_GATWH);
    cudaGetSymbolAddress((void**)&WOH, g_WOH);
    cudaGetSymbolAddress((void**)&W1H, g_W1H);
    cudaGetSymbolAddress((void**)&W2H, g_W2H);
    cudaGetSymbolAddress((void**)&AOH, g_AOH);
    cudaGetSymbolAddress((void**)&Y,  g_Y);
    cudaGetSymbolAddress((void**)&YH, g_YH);
    cudaGetSymbolAddress((void**)&FFH, g_FFH);
    cudaGetSymbolAddress((void**)&PART, g_PART);
    cudaGetSymbolAddress((void**)&BITS, g_BITS);
    cudaGetSymbolAddress((void**)&NBR, g_NBR);
    cudaGetSymbolAddress((void**)&CNT, g_CNT);

    const int M = MTOT;

    pack_adj_k<<<(BB*32*NNODE)/256, 256>>>(mask, BITS);
    build_nbr_k<<<(MTOT)/256, 256>>>(BITS, NBR, CNT);
    pack_qkv_k<<<(LTN*DD*3*DD + 255)/256, 256>>>(Wq, Wk, Wv, bq, bk, bv, WQKVH, BQKV);
    cvt_all_k<<<(CV_TOT/4 + 255)/256, 256>>>(emb, gatW, Wo, W1, W2);

    // ---- GAT stack ----
    const __half* x = EMBH;
    for (int l = 0; l < LGN; l++) {
        hgemm_k<true,0,1,1,1><<<dim3((HH*DD)/128, M/128), 256>>>(
            M, HH*DD, DD, x, DD, GATWH + (size_t)l*HH*DD*DD, DD,
            HBH, HH*DD, nullptr, attS + l*HH*DD, attD + l*HH*DD, ASP, ADP);
        asad_reduce_k<<<(MTOT*8)/256, 256>>>(ASP, ADP, AS, AD);
        gat_agg_k<<<M, 256>>>(HBH, AS, AD, NBR, CNT, gatB + l*DD, Y, YH);
        x = YH;
    }
    ln_warp_k<1,1><<<M/8, 256>>>(emb, Y, glnS, glnB, XC, XCH, nullptr);

    // ---- transformer layers ----
    for (int l = 0; l < LTN; l++) {
        hgemm_k<false,0,1,0,1><<<dim3((3*DD)/128, M/128), 256>>>(
            M, 3*DD, DD, XCH, DD, WQKVH + (size_t)l*DD*3*DD, 3*DD, QKVH, 3*DD,
            BQKV + l*3*DD, nullptr, nullptr, nullptr, nullptr);
        attn_sparse_k<<<M, 256>>>(QKVH, NBR, CNT, AOH);
        hgemm_k<false,0,0,0,1><<<dim3(DD/128, M/128), 256>>>(
            M, DD, DD, AOH, DD, WOH + (size_t)l*DD*DD, DD, Y, DD,
            bo + l*DD, nullptr, nullptr, nullptr, nullptr);
        ln_warp_k<0,1><<<M/8, 256>>>(XC, Y, l1s + l*DD, l1b + l*DD, XC, XCH, nullptr);
        hgemm_k<false,1,1,0,1><<<dim3(DFFX/128, M/128), 256>>>(
            M, DFFX, DD, XCH, DD, W1H + (size_t)l*DD*DFFX, DFFX, FFH, DFFX,
            b1 + l*DFFX, nullptr, nullptr, nullptr, nullptr);
        // FFN2: split-K=4 into PART; LN consumes partials directly (MODE 2)
        hgemm_k<false,0,0,0,SPLK><<<dim3(DD/128, M/128, SPLK), 256>>>(
            M, DD, DFFX, FFH, DFFX, W2H + (size_t)l*DFFX*DD, DD, PART, DD,
            nullptr, nullptr, nullptr, nullptr, nullptr);
        if (l == LTN - 1)
            ln_warp_k<2,0><<<M/8, 256>>>(XC, PART, l2s + l*DD, l2b + l*DD, out, nullptr, b2 + l*DD);
        else
            ln_warp_k<2,1><<<M/8, 256>>>(XC, PART, l2s + l*DD, l2b + l*DD, XC, XCH, b2 + l*DD);
    }
}